// round 13
// baseline (speedup 1.0000x reference)
#include <cuda_runtime.h>
#include <cuda_fp16.h>
#include <cstdint>
#include <cstddef>

// ============================================================================
// AttentionNetwork: P=4096, LMAX=64, D=512, H=512  (fp16 mma.sync path)
// R13: 128-thread CTAs (4 warps, 256-reg budget), warp tile 64x64
// (128B LDSM per MMA -> crossbar decoupled from tensor pipe), warp-PRIVATE
// 6-slot cp.async rings (no mainloop barriers at all), double-buffered
// fragments. occ 2 (112KB SMEM). k_agg/tails unchanged from R12.
// ============================================================================

#define NPATHS 4096

// ---------------- device scratch --------------------------------------------
__device__ __half g_W1T[512 * 512];   // pW1^T  [n][k]
__device__ __half g_aW1T[512 * 512];  // aW1^T  [n][k]
__device__ float g_pf[NPATHS * 512];  // paths_fea
__device__ float g_a[NPATHS];         // path logits (accumulated)
__device__ float g_aw[NPATHS];        // path softmax weights
__device__ float g_part[64 * 512];    // reduction partials

// ---------------- k_path SMEM layout (bytes) ----------------------------------
#define OFF_XS   0            // X tile: 64 rows x 1024B, XOR-swizzled
#define OFF_WR   65536        // 4 warps x 6 slots x 2048B = 49152
#define OFF_SC   65536        // overlays ring after mainloop (64 floats)
#define OFF_WTS  65792        // overlays ring (64 floats)
#define SMEM_PATH 114688      // 112KB -> 2 CTAs/SM

// ---------------- k_agg SMEM layout ------------------------------------------
#define AG_SC    0
#define AG_B1    1024
#define AG_W2    3072
#define AG_XS    5120         // 64 rows x 1040B
#define AG_XSTR  1040
#define AG_WSTR  144
#define OFFWS_AGG 71680
#define SMEM_AGG  (71680 + 4 * 36864)   // 219136

// ---------------- PTX helpers ------------------------------------------------
__device__ __forceinline__ uint32_t smem_u32(const void* p) {
    uint32_t a;
    asm("{ .reg .u64 t; cvta.to.shared.u64 t, %1; cvt.u32.u64 %0, t; }"
        : "=r"(a) : "l"(p));
    return a;
}

__device__ __forceinline__ void ldsm4(uint32_t* r, uint32_t addr) {
    asm volatile("ldmatrix.sync.aligned.m8n8.x4.shared.b16 {%0,%1,%2,%3}, [%4];"
                 : "=r"(r[0]), "=r"(r[1]), "=r"(r[2]), "=r"(r[3]) : "r"(addr));
}

__device__ __forceinline__ void mma_f16(float* c, const uint32_t* a,
                                        uint32_t b0, uint32_t b1) {
    asm volatile(
        "mma.sync.aligned.m16n8k16.row.col.f32.f16.f16.f32 "
        "{%0,%1,%2,%3}, {%4,%5,%6,%7}, {%8,%9}, {%0,%1,%2,%3};"
        : "+f"(c[0]), "+f"(c[1]), "+f"(c[2]), "+f"(c[3])
        : "r"(a[0]), "r"(a[1]), "r"(a[2]), "r"(a[3]), "r"(b0), "r"(b1));
}

#define CP_ASYNC16(dst, src) \
    asm volatile("cp.async.cg.shared.global [%0], [%1], 16;" \
                 :: "r"(dst), "l"(src) : "memory")
#define CP_COMMIT() asm volatile("cp.async.commit_group;" ::: "memory")
#define CP_WAIT(n)  asm volatile("cp.async.wait_group %0;" :: "n"(n) : "memory")

// convert one float4 -> 8B (2x half2) and store to SMEM
__device__ __forceinline__ void sts_f16x4(char* smem, uint32_t off, float4 v) {
    __half2 p0, p1;
    p0.x = __float2half_rn(v.x); p0.y = __float2half_rn(v.y);
    p1.x = __float2half_rn(v.z); p1.y = __float2half_rn(v.w);
    uint2 st;
    st.x = *(uint32_t*)&p0;
    st.y = *(uint32_t*)&p1;
    *(uint2*)(smem + off) = st;
}

// ============================================================================
//                       k_path (R13)
// ============================================================================

// prefetch W chunk c (= pass*32 + kc) for THIS warp's n-slice:
// rows [pass*256 + w*64, +64), k [kc*16, +16) -> warp ring slot c%6.
__device__ __forceinline__ void prefetch_Wc(const __half* __restrict__ Wt,
                                            int c, uint32_t ringBase,
                                            int w, int lane) {
    int pass = c >> 5, kc = c & 31;
    uint32_t slotbase = ringBase + (uint32_t)(c % 6) * 2048;
    const __half* src = Wt + (size_t)(pass * 256 + w * 64) * 512 + kc * 16;
#pragma unroll
    for (int i = 0; i < 4; i++) {
        int idx = lane + i * 32;          // 0..127 (16B units)
        int nl = idx >> 1;                // 0..63 row
        int q  = (idx & 1) << 4;          // 0 or 16 bytes
        uint32_t dst = slotbase + nl * 32 + (q ^ (((nl >> 2) & 1) << 4));
        CP_ASYNC16(dst, src + (size_t)nl * 512 + (q >> 1));
    }
    CP_COMMIT();
}

__global__ void __launch_bounds__(128, 2)
k_path(const float* __restrict__ nodes, const int* __restrict__ lengths,
       const float* __restrict__ pb1, const float* __restrict__ pw2,
       const float* __restrict__ pb2) {
    extern __shared__ char smem[];
    uint32_t sb = smem_u32(smem);
    int tid = threadIdx.x;
    int lane = tid & 31, wid = tid >> 5;      // wid = n-slice owner (0..3)
    uint32_t ringBase = sb + OFF_WR + wid * (6 * 2048);

    // warp-private W stream: prefetch chunks 0..4 (prologue, distance 5)
#pragma unroll
    for (int c = 0; c < 5; c++) prefetch_Wc(g_W1T, c, ringBase, wid, lane);

    // load X: 64 rows x 512 fp32 -> fp16, XOR-swizzled, stride 1024B
    const float* X = nodes + (size_t)blockIdx.x * 64 * 512;
#pragma unroll 4
    for (int i = 0; i < 64; i++) {
        int idx = tid + i * 128;          // 0..8191 float4 slots
        int m = idx >> 7;                 // 128 float4 per row
        int q = idx & 127;
        float4 v = *(const float4*)(X + (size_t)m * 512 + q * 4);
        uint32_t cb = (uint32_t)(q * 8);
        uint32_t off = OFF_XS + m * 1024 + (cb ^ (((uint32_t)(m & 7)) << 4));
        sts_f16x4(smem, off, v);
    }
    __syncthreads();                      // publish X

    // per-lane ldmatrix bases
    int lr = lane & 7;
    uint32_t aswz = (uint32_t)lr << 4;                 // X swizzle mask
    uint32_t a16  = (uint32_t)((lane >> 4) & 1) << 4;  // k 16B-half select
    uint32_t aRow[4];
#pragma unroll
    for (int mi = 0; mi < 4; mi++)
        aRow[mi] = sb + OFF_XS +
                   (mi * 16 + ((lane >> 3) & 1) * 8 + lr) * 1024;
    uint32_t bB[4];                        // within-slot B bases
#pragma unroll
    for (int nj = 0; nj < 4; nj++) {
        int row = nj * 16 + ((lane >> 4) & 1) * 8 + lr;
        uint32_t csel = (uint32_t)((lane >> 3) & 1) << 4;
        uint32_t bswz = (uint32_t)((lr >> 2) & 1) << 4;
        bB[nj] = ringBase + row * 32 + (csel ^ bswz);
    }

    float acc[4][8][4];                   // 128 accumulator regs
#pragma unroll
    for (int mi = 0; mi < 4; mi++)
#pragma unroll
        for (int nq = 0; nq < 8; nq++)
#pragma unroll
            for (int q = 0; q < 4; q++) acc[mi][nq][q] = 0.f;
    float rs[8];
#pragma unroll
    for (int i = 0; i < 8; i++) rs[i] = 0.f;

    // fragment double buffers
    uint32_t Af[2][4][4], Bf[2][4][4];

    // chunk 0 frags
    CP_WAIT(4);
    {
        uint32_t kb = 0;
#pragma unroll
        for (int mi = 0; mi < 4; mi++)
            ldsm4(Af[0][mi], aRow[mi] + ((kb | a16) ^ aswz));
#pragma unroll
        for (int nj = 0; nj < 4; nj++)
            ldsm4(Bf[0][nj], bB[nj] + 0 * 2048);
    }

    // mainloop: 64 k16 chunks = 2 N-passes x 32. NO barriers, warp-private.
    for (int c = 0; c < 64; c++) {
        int cur = c & 1, nxt = cur ^ 1;
        if (c + 5 < 64) prefetch_Wc(g_W1T, c + 5, ringBase, wid, lane);
        else CP_COMMIT();                 // keep group count aligned
        if (c + 1 < 64) {
            CP_WAIT(4);                   // chunk c+1 landed
            uint32_t kb = (uint32_t)((c + 1) & 31) * 32;
            uint32_t slot = (uint32_t)((c + 1) % 6) * 2048;
#pragma unroll
            for (int mi = 0; mi < 4; mi++)
                ldsm4(Af[nxt][mi], aRow[mi] + ((kb | a16) ^ aswz));
#pragma unroll
            for (int nj = 0; nj < 4; nj++)
                ldsm4(Bf[nxt][nj], bB[nj] + slot);
        }
#pragma unroll
        for (int mi = 0; mi < 4; mi++)
#pragma unroll
            for (int nj = 0; nj < 4; nj++) {
                mma_f16(acc[mi][nj * 2],     Af[cur][mi], Bf[cur][nj][0], Bf[cur][nj][1]);
                mma_f16(acc[mi][nj * 2 + 1], Af[cur][mi], Bf[cur][nj][2], Bf[cur][nj][3]);
            }

        if ((c & 31) == 31) {
            // fold this 256-wide N pass into per-row score partials
            int pass = c >> 5;
            int t2 = (lane & 3) * 2;
#pragma unroll
            for (int mi = 0; mi < 4; mi++)
#pragma unroll
                for (int nq = 0; nq < 8; nq++) {
                    int n0 = pass * 256 + wid * 64 + nq * 8 + t2;
                    float2 bb = __ldg((const float2*)(pb1 + n0));
                    float2 ww = __ldg((const float2*)(pw2 + n0));
                    float* cc = acc[mi][nq];
                    rs[mi * 2 + 0] += fmaxf(cc[0] + bb.x, 0.f) * ww.x +
                                      fmaxf(cc[1] + bb.y, 0.f) * ww.y;
                    rs[mi * 2 + 1] += fmaxf(cc[2] + bb.x, 0.f) * ww.x +
                                      fmaxf(cc[3] + bb.y, 0.f) * ww.y;
                    cc[0] = cc[1] = cc[2] = cc[3] = 0.f;
                }
        }
    }

    // ring is dead after ALL warps pass this barrier; overlay sc/wts on it
    __syncthreads();
    float* sc = (float*)(smem + OFF_SC);
    if (tid < 64) sc[tid] = 0.f;
    __syncthreads();

    // reduce the 4 lanes sharing each row, combine the 4 n-slice warps
#pragma unroll
    for (int i = 0; i < 8; i++) {
        rs[i] += __shfl_xor_sync(0xffffffffu, rs[i], 1);
        rs[i] += __shfl_xor_sync(0xffffffffu, rs[i], 2);
    }
    if ((lane & 3) == 0) {
        int g = lane >> 2;
#pragma unroll
        for (int mi = 0; mi < 4; mi++) {
            atomicAdd(&sc[mi * 16 + g],     rs[mi * 2 + 0]);
            atomicAdd(&sc[mi * 16 + 8 + g], rs[mi * 2 + 1]);
        }
    }
    __syncthreads();

    // masked softmax over this path's 64 positions
    if (tid < 64) {
        int len = lengths[blockIdx.x];
        float mx = -1e30f;
        for (int j = 0; j < 64; j++) if (j < len) mx = fmaxf(mx, sc[j]);
        float sum = 0.f;
        for (int j = 0; j < 64; j++) if (j < len) sum += expf(sc[j] - mx);
        float w = (tid < len) ? expf(sc[tid] - mx) / sum : 0.f;
        ((float*)(smem + OFF_WTS))[tid] = w;
    }
    __syncthreads();

    // weighted sum of X rows (fp16, swizzled) -> paths_fea
    const float* wts = (const float*)(smem + OFF_WTS);
#pragma unroll
    for (int it = 0; it < 2; it++) {
        int dp = tid + it * 128;          // fp16x2 column (0..255)
        float a0 = 0.f, a1 = 0.f;
        uint32_t cbyte = (uint32_t)dp * 4;
#pragma unroll 8
        for (int l = 0; l < 64; l++) {
            uint32_t off = OFF_XS + l * 1024 +
                           (cbyte ^ (((uint32_t)(l & 7)) << 4));
            uint32_t v = *(const uint32_t*)(smem + off);
            __half2 hv = *(__half2*)&v;
            float wl = wts[l];
            a0 = fmaf(wl, __half2float(hv.x), a0);
            a1 = fmaf(wl, __half2float(hv.y), a1);
        }
        float* dst = g_pf + (size_t)blockIdx.x * 512 + dp * 2;
        dst[0] = a0;
        dst[1] = a1;
    }
}

// ============================================================================
//          k_agg (R11: grid 128 = 64 row-blocks x 2 N-halves)
// ============================================================================

__device__ __forceinline__ void ag_prefetch(const __half* __restrict__ Wt,
                                            int s, int buf, uint32_t sb) {
    int tid = threadIdx.x;
    const __half* src = Wt + s * 64;      // chunk s: rows [0,256), k [s*64,+64)
#pragma unroll
    for (int i = 0; i < 8; i++) {
        int idx = tid + i * 256;
        int nl = idx >> 3;
        int q  = idx & 7;
        uint32_t dst = sb + OFFWS_AGG + buf * 36864 + nl * AG_WSTR + q * 16;
        CP_ASYNC16(dst, src + (size_t)nl * 512 + q * 8);
    }
    CP_COMMIT();
}

__global__ void __launch_bounds__(256, 1)
k_agg(const float* __restrict__ ab1, const float* __restrict__ aw2,
      const float* __restrict__ ab2) {
    extern __shared__ char smem[];
    uint32_t sb = smem_u32(smem);
    int tid = threadIdx.x;
    int lane = tid & 31, wid = tid >> 5;
    int n_part = wid;                     // 32-col slice of this 256-N-half
    int rb = blockIdx.x >> 1;             // row block (64 paths)
    int h  = blockIdx.x & 1;              // N half
    const __half* Wt = g_aW1T + (size_t)h * 256 * 512;

    ag_prefetch(Wt, 0, 0, sb);
    ag_prefetch(Wt, 1, 1, sb);
    ag_prefetch(Wt, 2, 2, sb);

    float* b1s = (float*)(smem + AG_B1);
    float* w2s = (float*)(smem + AG_W2);
    float* sc  = (float*)(smem + AG_SC);
    for (int i = tid; i < 512; i += 256) { b1s[i] = ab1[i]; w2s[i] = aw2[i]; }
    if (tid < 64) sc[tid] = 0.f;

    const float* X = g_pf + (size_t)rb * 64 * 512;
#pragma unroll 4
    for (int i = 0; i < 32; i++) {
        int idx = tid + i * 256;
        int m = idx >> 7;
        int q = idx & 127;
        float4 v = *(const float4*)(X + (size_t)m * 512 + q * 4);
        sts_f16x4(smem, AG_XS + m * AG_XSTR + q * 8, v);
    }

    int lr = lane & 7;
    uint32_t aA[4];
#pragma unroll
    for (int mi = 0; mi < 4; mi++)
        aA[mi] = sb + AG_XS +
                 (mi * 16 + ((lane >> 3) & 1) * 8 + lr) * AG_XSTR +
                 (lane >> 4) * 16;
    uint32_t bA[2];
#pragma unroll
    for (int nj = 0; nj < 2; nj++)
        bA[nj] = sb + OFFWS_AGG +
                 (n_part * 32 + nj * 16 + (lane >> 4) * 8 + lr) * AG_WSTR +
                 ((lane >> 3) & 1) * 16;

    float acc[4][4][4];
#pragma unroll
    for (int mi = 0; mi < 4; mi++)
#pragma unroll
        for (int nq = 0; nq < 4; nq++)
#pragma unroll
            for (int q = 0; q < 4; q++) acc[mi][nq][q] = 0.f;
    float rs[8];
#pragma unroll
    for (int i = 0; i < 8; i++) rs[i] = 0.f;

    for (int s = 0; s < 8; s++) {         // 8 k-chunks (k64 each), 1 N-half
        __syncthreads();
        if (s + 3 < 8) ag_prefetch(Wt, s + 3, (s + 3) & 3, sb);
        else CP_COMMIT();
        CP_WAIT(3);
        __syncthreads();

        uint32_t buf = (uint32_t)(s & 3) * 36864;
#pragma unroll
        for (int k16 = 0; k16 < 4; k16++) {
            uint32_t kxX = s * 128 + k16 * 32;
            uint32_t kxW = k16 * 32;
            uint32_t A[4][4], B[2][4];
#pragma unroll
            for (int mi = 0; mi < 4; mi++) ldsm4(A[mi], aA[mi] + kxX);
#pragma unroll
            for (int nj = 0; nj < 2; nj++) ldsm4(B[nj], bA[nj] + buf + kxW);
#pragma unroll
            for (int mi = 0; mi < 4; mi++)
#pragma unroll
                for (int nj = 0; nj < 2; nj++) {
                    mma_f16(acc[mi][nj * 2],     A[mi], B[nj][0], B[nj][1]);
                    mma_f16(acc[mi][nj * 2 + 1], A[mi], B[nj][2], B[nj][3]);
                }
        }
    }

    // fold the 256-wide N half
    {
        int t2 = (lane & 3) * 2;
#pragma unroll
        for (int mi = 0; mi < 4; mi++)
#pragma unroll
            for (int nq = 0; nq < 4; nq++) {
                int n0 = h * 256 + n_part * 32 + nq * 8 + t2;
                float bb0 = b1s[n0], bb1 = b1s[n0 + 1];
                float ww0 = w2s[n0], ww1 = w2s[n0 + 1];
                float* cc = acc[mi][nq];
                rs[mi * 2 + 0] += fmaxf(cc[0] + bb0, 0.f) * ww0 +
                                  fmaxf(cc[1] + bb1, 0.f) * ww1;
                rs[mi * 2 + 1] += fmaxf(cc[2] + bb0, 0.f) * ww0 +
                                  fmaxf(cc[3] + bb1, 0.f) * ww1;
            }
    }

#pragma unroll
    for (int i = 0; i < 8; i++) {
        rs[i] += __shfl_xor_sync(0xffffffffu, rs[i], 1);
        rs[i] += __shfl_xor_sync(0xffffffffu, rs[i], 2);
    }
    if ((lane & 3) == 0) {
        int g = lane >> 2;
#pragma unroll
        for (int mi = 0; mi < 4; mi++) {
            atomicAdd(&sc[mi * 16 + g],     rs[mi * 2 + 0]);
            atomicAdd(&sc[mi * 16 + 8 + g], rs[mi * 2 + 1]);
        }
    }
    __syncthreads();

    // accumulate partial logits (g_a pre-zeroed by k_zero)
    if (tid < 64)
        atomicAdd(&g_a[rb * 64 + tid], sc[tid] + (h == 0 ? ab2[0] : 0.f));
}

// ---------------- kernel 0: transpose + convert weights ----------------------
__global__ void k_conv(const float* __restrict__ src, __half* __restrict__ dst) {
    __shared__ float tile[64][65];
    int k0 = blockIdx.y * 64, n0 = blockIdx.x * 64;
    for (int i = threadIdx.x; i < 4096; i += 256) {
        int r = i >> 6, cth = i & 63;
        tile[r][cth] = src[(size_t)(k0 + r) * 512 + n0 + cth];
    }
    __syncthreads();
    for (int i = threadIdx.x; i < 4096; i += 256) {
        int r = i >> 6, cth = i & 63;
        dst[(size_t)(n0 + r) * 512 + k0 + cth] = __float2half_rn(tile[cth][r]);
    }
}

// ---------------- kernel 0b: zero g_a (also keeps k_path at ncu slot) ---------
__global__ void k_zero() {
    g_a[blockIdx.x * 64 + threadIdx.x] = 0.f;   // k_agg accumulates into this
}

// ---------------- kernel 3: softmax over 4096 paths ---------------------------
__global__ void k_soft() {
    __shared__ float red[1024];
    int t = threadIdx.x;
    float m = -1e30f;
    for (int i = t; i < NPATHS; i += 1024) m = fmaxf(m, g_a[i]);
    red[t] = m;
    __syncthreads();
    for (int s = 512; s > 0; s >>= 1) {
        if (t < s) red[t] = fmaxf(red[t], red[t + s]);
        __syncthreads();
    }
    float M = red[0];
    __syncthreads();
    float sum = 0.f;
    for (int i = t; i < NPATHS; i += 1024) sum += expf(g_a[i] - M);
    red[t] = sum;
    __syncthreads();
    for (int s = 512; s > 0; s >>= 1) {
        if (t < s) red[t] += red[t + s];
        __syncthreads();
    }
    float S = red[0];
    for (int i = t; i < NPATHS; i += 1024) g_aw[i] = expf(g_a[i] - M) / S;
}

// ---------------- kernel 4: partial weighted sums -----------------------------
__global__ void k_red() {
    int b = blockIdx.x, t = threadIdx.x;
    float a0 = 0.f, a1 = 0.f;
    for (int p = 0; p < 64; p++) {
        int pg = b * 64 + p;
        float w = g_aw[pg];
        const float* row = g_pf + (size_t)pg * 512;
        a0 = fmaf(w, row[t], a0);
        a1 = fmaf(w, row[t + 256], a1);
    }
    g_part[(size_t)b * 512 + t] = a0;
    g_part[(size_t)b * 512 + t + 256] = a1;
}

// ---------------- kernel 5: final reduction -----------------------------------
__global__ void k_fin(float* __restrict__ out) {
    int t = threadIdx.x;
    float s = 0.f;
    for (int b = 0; b < 64; b++) s += g_part[(size_t)b * 512 + t];
    out[t] = s;
}

// ---------------- entry -------------------------------------------------------
extern "C" void kernel_launch(void* const* d_in, const int* in_sizes, int n_in,
                              void* d_out, int out_size) {
    const float* nodes   = (const float*)d_in[0];
    const int*   lengths = (const int*)  d_in[1];
    const float* pW1     = (const float*)d_in[2];
    const float* pb1     = (const float*)d_in[3];
    const float* pw2     = (const float*)d_in[4];
    const float* pb2     = (const float*)d_in[5];
    const float* aW1     = (const float*)d_in[6];
    const float* ab1     = (const float*)d_in[7];
    const float* aw2     = (const float*)d_in[8];
    const float* ab2     = (const float*)d_in[9];
    float* out = (float*)d_out;
    (void)pb2;

    cudaFuncSetAttribute(k_path, cudaFuncAttributeMaxDynamicSharedMemorySize, SMEM_PATH);
    cudaFuncSetAttribute(k_agg,  cudaFuncAttributeMaxDynamicSharedMemorySize, SMEM_AGG);

    __half* w1t;  cudaGetSymbolAddress((void**)&w1t,  g_W1T);
    __half* aw1t; cudaGetSymbolAddress((void**)&aw1t, g_aW1T);

    k_conv<<<dim3(8, 8), 256>>>(pW1, w1t);     // idx 0
    k_conv<<<dim3(8, 8), 256>>>(aW1, aw1t);    // idx 1
    k_zero<<<64, 64>>>();                      // idx 2 (zeroes g_a; ncu slot)
    k_path<<<NPATHS, 128, SMEM_PATH>>>(nodes, lengths, pb1, pw2, pb2);  // idx 3
    k_agg<<<128, 256, SMEM_AGG>>>(ab1, aw2, ab2);                       // idx 4
    k_soft<<<1, 1024>>>();
    k_red<<<64, 256>>>();
    k_fin<<<1, 512>>>(out);
}

// round 14
// speedup vs baseline: 1.5727x; 1.5727x over previous
#include <cuda_runtime.h>
#include <cuda_fp16.h>
#include <cstdint>
#include <cstddef>

// ============================================================================
// AttentionNetwork: P=4096, LMAX=64, D=512, H=512  (fp16 mma.sync path)
// R14 = R13 with the mainloop unrolled x2 so the fragment double-buffer
// indices (cur/nxt) are COMPILE-TIME -> frags stay in registers (R13 demoted
// them to local memory via dynamic indexing, causing the 2.3x regression).
// 128-thread CTAs, warp tile 64x64, warp-private 6-slot cp.async rings,
// no mainloop barriers, occ 2 (112KB SMEM).
// ============================================================================

#define NPATHS 4096

// ---------------- device scratch --------------------------------------------
__device__ __half g_W1T[512 * 512];   // pW1^T  [n][k]
__device__ __half g_aW1T[512 * 512];  // aW1^T  [n][k]
__device__ float g_pf[NPATHS * 512];  // paths_fea
__device__ float g_a[NPATHS];         // path logits (accumulated)
__device__ float g_aw[NPATHS];        // path softmax weights
__device__ float g_part[64 * 512];    // reduction partials

// ---------------- k_path SMEM layout (bytes) ----------------------------------
#define OFF_XS   0            // X tile: 64 rows x 1024B, XOR-swizzled
#define OFF_WR   65536        // 4 warps x 6 slots x 2048B = 49152
#define OFF_SC   65536        // overlays ring after mainloop (64 floats)
#define OFF_WTS  65792        // overlays ring (64 floats)
#define SMEM_PATH 114688      // 112KB -> 2 CTAs/SM

// ---------------- k_agg SMEM layout ------------------------------------------
#define AG_SC    0
#define AG_B1    1024
#define AG_W2    3072
#define AG_XS    5120         // 64 rows x 1040B
#define AG_XSTR  1040
#define AG_WSTR  144
#define OFFWS_AGG 71680
#define SMEM_AGG  (71680 + 4 * 36864)   // 219136

// ---------------- PTX helpers ------------------------------------------------
__device__ __forceinline__ uint32_t smem_u32(const void* p) {
    uint32_t a;
    asm("{ .reg .u64 t; cvta.to.shared.u64 t, %1; cvt.u32.u64 %0, t; }"
        : "=r"(a) : "l"(p));
    return a;
}

__device__ __forceinline__ void ldsm4(uint32_t* r, uint32_t addr) {
    asm volatile("ldmatrix.sync.aligned.m8n8.x4.shared.b16 {%0,%1,%2,%3}, [%4];"
                 : "=r"(r[0]), "=r"(r[1]), "=r"(r[2]), "=r"(r[3]) : "r"(addr));
}

__device__ __forceinline__ void mma_f16(float* c, const uint32_t* a,
                                        uint32_t b0, uint32_t b1) {
    asm volatile(
        "mma.sync.aligned.m16n8k16.row.col.f32.f16.f16.f32 "
        "{%0,%1,%2,%3}, {%4,%5,%6,%7}, {%8,%9}, {%0,%1,%2,%3};"
        : "+f"(c[0]), "+f"(c[1]), "+f"(c[2]), "+f"(c[3])
        : "r"(a[0]), "r"(a[1]), "r"(a[2]), "r"(a[3]), "r"(b0), "r"(b1));
}

#define CP_ASYNC16(dst, src) \
    asm volatile("cp.async.cg.shared.global [%0], [%1], 16;" \
                 :: "r"(dst), "l"(src) : "memory")
#define CP_COMMIT() asm volatile("cp.async.commit_group;" ::: "memory")
#define CP_WAIT(n)  asm volatile("cp.async.wait_group %0;" :: "n"(n) : "memory")

// convert one float4 -> 8B (2x half2) and store to SMEM
__device__ __forceinline__ void sts_f16x4(char* smem, uint32_t off, float4 v) {
    __half2 p0, p1;
    p0.x = __float2half_rn(v.x); p0.y = __float2half_rn(v.y);
    p1.x = __float2half_rn(v.z); p1.y = __float2half_rn(v.w);
    uint2 st;
    st.x = *(uint32_t*)&p0;
    st.y = *(uint32_t*)&p1;
    *(uint2*)(smem + off) = st;
}

// ============================================================================
//                       k_path (R14)
// ============================================================================

// prefetch W chunk c (= pass*32 + kc) for THIS warp's n-slice:
// rows [pass*256 + w*64, +64), k [kc*16, +16) -> warp ring slot c%6.
__device__ __forceinline__ void prefetch_Wc(const __half* __restrict__ Wt,
                                            int c, uint32_t ringBase,
                                            int w, int lane) {
    int pass = c >> 5, kc = c & 31;
    uint32_t slotbase = ringBase + (uint32_t)(c % 6) * 2048;
    const __half* src = Wt + (size_t)(pass * 256 + w * 64) * 512 + kc * 16;
#pragma unroll
    for (int i = 0; i < 4; i++) {
        int idx = lane + i * 32;          // 0..127 (16B units)
        int nl = idx >> 1;                // 0..63 row
        int q  = (idx & 1) << 4;          // 0 or 16 bytes
        uint32_t dst = slotbase + nl * 32 + (q ^ (((nl >> 2) & 1) << 4));
        CP_ASYNC16(dst, src + (size_t)nl * 512 + (q >> 1));
    }
    CP_COMMIT();
}

__global__ void __launch_bounds__(128, 2)
k_path(const float* __restrict__ nodes, const int* __restrict__ lengths,
       const float* __restrict__ pb1, const float* __restrict__ pw2,
       const float* __restrict__ pb2) {
    extern __shared__ char smem[];
    uint32_t sb = smem_u32(smem);
    int tid = threadIdx.x;
    int lane = tid & 31, wid = tid >> 5;      // wid = n-slice owner (0..3)
    uint32_t ringBase = sb + OFF_WR + wid * (6 * 2048);

    // warp-private W stream: prefetch chunks 0..4 (prologue, distance 5)
#pragma unroll
    for (int c = 0; c < 5; c++) prefetch_Wc(g_W1T, c, ringBase, wid, lane);

    // load X: 64 rows x 512 fp32 -> fp16, XOR-swizzled, stride 1024B
    const float* X = nodes + (size_t)blockIdx.x * 64 * 512;
#pragma unroll 4
    for (int i = 0; i < 64; i++) {
        int idx = tid + i * 128;          // 0..8191 float4 slots
        int m = idx >> 7;                 // 128 float4 per row
        int q = idx & 127;
        float4 v = *(const float4*)(X + (size_t)m * 512 + q * 4);
        uint32_t cb = (uint32_t)(q * 8);
        uint32_t off = OFF_XS + m * 1024 + (cb ^ (((uint32_t)(m & 7)) << 4));
        sts_f16x4(smem, off, v);
    }
    __syncthreads();                      // publish X

    // per-lane ldmatrix bases
    int lr = lane & 7;
    uint32_t aswz = (uint32_t)lr << 4;                 // X swizzle mask
    uint32_t a16  = (uint32_t)((lane >> 4) & 1) << 4;  // k 16B-half select
    uint32_t aRow[4];
#pragma unroll
    for (int mi = 0; mi < 4; mi++)
        aRow[mi] = sb + OFF_XS +
                   (mi * 16 + ((lane >> 3) & 1) * 8 + lr) * 1024;
    uint32_t bB[4];                        // within-slot B bases
#pragma unroll
    for (int nj = 0; nj < 4; nj++) {
        int row = nj * 16 + ((lane >> 4) & 1) * 8 + lr;
        uint32_t csel = (uint32_t)((lane >> 3) & 1) << 4;
        uint32_t bswz = (uint32_t)((lr >> 2) & 1) << 4;
        bB[nj] = ringBase + row * 32 + (csel ^ bswz);
    }

    float acc[4][8][4];                   // 128 accumulator regs
#pragma unroll
    for (int mi = 0; mi < 4; mi++)
#pragma unroll
        for (int nq = 0; nq < 8; nq++)
#pragma unroll
            for (int q = 0; q < 4; q++) acc[mi][nq][q] = 0.f;
    float rs[8];
#pragma unroll
    for (int i = 0; i < 8; i++) rs[i] = 0.f;

    // fragment double buffers (indices are compile-time after unroll-2)
    uint32_t Af[2][4][4], Bf[2][4][4];

    // chunk 0 frags
    CP_WAIT(4);
    {
        uint32_t kb = 0;
#pragma unroll
        for (int mi = 0; mi < 4; mi++)
            ldsm4(Af[0][mi], aRow[mi] + ((kb | a16) ^ aswz));
#pragma unroll
        for (int nj = 0; nj < 4; nj++)
            ldsm4(Bf[0][nj], bB[nj] + 0 * 2048);
    }

    // mainloop: 64 k16 chunks = 2 N-passes x 32. NO barriers, warp-private.
    // UNROLL 2 is load-bearing: makes (c&1) compile-time so Af/Bf stay in
    // registers (dynamic indexing demotes them to local memory).
#pragma unroll 2
    for (int c = 0; c < 64; c++) {
        const int cur = c & 1, nxt = cur ^ 1;
        if (c + 5 < 64) prefetch_Wc(g_W1T, c + 5, ringBase, wid, lane);
        else CP_COMMIT();                 // keep group count aligned
        if (c + 1 < 64) {
            CP_WAIT(4);                   // chunk c+1 landed
            uint32_t kb = (uint32_t)((c + 1) & 31) * 32;
            uint32_t slot = (uint32_t)((c + 1) % 6) * 2048;
#pragma unroll
            for (int mi = 0; mi < 4; mi++)
                ldsm4(Af[nxt][mi], aRow[mi] + ((kb | a16) ^ aswz));
#pragma unroll
            for (int nj = 0; nj < 4; nj++)
                ldsm4(Bf[nxt][nj], bB[nj] + slot);
        }
#pragma unroll
        for (int mi = 0; mi < 4; mi++)
#pragma unroll
            for (int nj = 0; nj < 4; nj++) {
                mma_f16(acc[mi][nj * 2],     Af[cur][mi], Bf[cur][nj][0], Bf[cur][nj][1]);
                mma_f16(acc[mi][nj * 2 + 1], Af[cur][mi], Bf[cur][nj][2], Bf[cur][nj][3]);
            }

        if ((c & 31) == 31) {
            // fold this 256-wide N pass into per-row score partials
            int pass = c >> 5;
            int t2 = (lane & 3) * 2;
#pragma unroll
            for (int mi = 0; mi < 4; mi++)
#pragma unroll
                for (int nq = 0; nq < 8; nq++) {
                    int n0 = pass * 256 + wid * 64 + nq * 8 + t2;
                    float2 bb = __ldg((const float2*)(pb1 + n0));
                    float2 ww = __ldg((const float2*)(pw2 + n0));
                    float* cc = acc[mi][nq];
                    rs[mi * 2 + 0] += fmaxf(cc[0] + bb.x, 0.f) * ww.x +
                                      fmaxf(cc[1] + bb.y, 0.f) * ww.y;
                    rs[mi * 2 + 1] += fmaxf(cc[2] + bb.x, 0.f) * ww.x +
                                      fmaxf(cc[3] + bb.y, 0.f) * ww.y;
                    cc[0] = cc[1] = cc[2] = cc[3] = 0.f;
                }
        }
    }

    // ring is dead after ALL warps pass this barrier; overlay sc/wts on it
    __syncthreads();
    float* sc = (float*)(smem + OFF_SC);
    if (tid < 64) sc[tid] = 0.f;
    __syncthreads();

    // reduce the 4 lanes sharing each row, combine the 4 n-slice warps
#pragma unroll
    for (int i = 0; i < 8; i++) {
        rs[i] += __shfl_xor_sync(0xffffffffu, rs[i], 1);
        rs[i] += __shfl_xor_sync(0xffffffffu, rs[i], 2);
    }
    if ((lane & 3) == 0) {
        int g = lane >> 2;
#pragma unroll
        for (int mi = 0; mi < 4; mi++) {
            atomicAdd(&sc[mi * 16 + g],     rs[mi * 2 + 0]);
            atomicAdd(&sc[mi * 16 + 8 + g], rs[mi * 2 + 1]);
        }
    }
    __syncthreads();

    // masked softmax over this path's 64 positions
    if (tid < 64) {
        int len = lengths[blockIdx.x];
        float mx = -1e30f;
        for (int j = 0; j < 64; j++) if (j < len) mx = fmaxf(mx, sc[j]);
        float sum = 0.f;
        for (int j = 0; j < 64; j++) if (j < len) sum += expf(sc[j] - mx);
        float w = (tid < len) ? expf(sc[tid] - mx) / sum : 0.f;
        ((float*)(smem + OFF_WTS))[tid] = w;
    }
    __syncthreads();

    // weighted sum of X rows (fp16, swizzled) -> paths_fea
    const float* wts = (const float*)(smem + OFF_WTS);
#pragma unroll
    for (int it = 0; it < 2; it++) {
        int dp = tid + it * 128;          // fp16x2 column (0..255)
        float a0 = 0.f, a1 = 0.f;
        uint32_t cbyte = (uint32_t)dp * 4;
#pragma unroll 8
        for (int l = 0; l < 64; l++) {
            uint32_t off = OFF_XS + l * 1024 +
                           (cbyte ^ (((uint32_t)(l & 7)) << 4));
            uint32_t v = *(const uint32_t*)(smem + off);
            __half2 hv = *(__half2*)&v;
            float wl = wts[l];
            a0 = fmaf(wl, __half2float(hv.x), a0);
            a1 = fmaf(wl, __half2float(hv.y), a1);
        }
        float* dst = g_pf + (size_t)blockIdx.x * 512 + dp * 2;
        dst[0] = a0;
        dst[1] = a1;
    }
}

// ============================================================================
//          k_agg (grid 128 = 64 row-blocks x 2 N-halves)
// ============================================================================

__device__ __forceinline__ void ag_prefetch(const __half* __restrict__ Wt,
                                            int s, int buf, uint32_t sb) {
    int tid = threadIdx.x;
    const __half* src = Wt + s * 64;      // chunk s: rows [0,256), k [s*64,+64)
#pragma unroll
    for (int i = 0; i < 8; i++) {
        int idx = tid + i * 256;
        int nl = idx >> 3;
        int q  = idx & 7;
        uint32_t dst = sb + OFFWS_AGG + buf * 36864 + nl * AG_WSTR + q * 16;
        CP_ASYNC16(dst, src + (size_t)nl * 512 + q * 8);
    }
    CP_COMMIT();
}

__global__ void __launch_bounds__(256, 1)
k_agg(const float* __restrict__ ab1, const float* __restrict__ aw2,
      const float* __restrict__ ab2) {
    extern __shared__ char smem[];
    uint32_t sb = smem_u32(smem);
    int tid = threadIdx.x;
    int lane = tid & 31, wid = tid >> 5;
    int n_part = wid;                     // 32-col slice of this 256-N-half
    int rb = blockIdx.x >> 1;             // row block (64 paths)
    int h  = blockIdx.x & 1;              // N half
    const __half* Wt = g_aW1T + (size_t)h * 256 * 512;

    ag_prefetch(Wt, 0, 0, sb);
    ag_prefetch(Wt, 1, 1, sb);
    ag_prefetch(Wt, 2, 2, sb);

    float* b1s = (float*)(smem + AG_B1);
    float* w2s = (float*)(smem + AG_W2);
    float* sc  = (float*)(smem + AG_SC);
    for (int i = tid; i < 512; i += 256) { b1s[i] = ab1[i]; w2s[i] = aw2[i]; }
    if (tid < 64) sc[tid] = 0.f;

    const float* X = g_pf + (size_t)rb * 64 * 512;
#pragma unroll 4
    for (int i = 0; i < 32; i++) {
        int idx = tid + i * 256;
        int m = idx >> 7;
        int q = idx & 127;
        float4 v = *(const float4*)(X + (size_t)m * 512 + q * 4);
        sts_f16x4(smem, AG_XS + m * AG_XSTR + q * 8, v);
    }

    int lr = lane & 7;
    uint32_t aA[4];
#pragma unroll
    for (int mi = 0; mi < 4; mi++)
        aA[mi] = sb + AG_XS +
                 (mi * 16 + ((lane >> 3) & 1) * 8 + lr) * AG_XSTR +
                 (lane >> 4) * 16;
    uint32_t bA[2];
#pragma unroll
    for (int nj = 0; nj < 2; nj++)
        bA[nj] = sb + OFFWS_AGG +
                 (n_part * 32 + nj * 16 + (lane >> 4) * 8 + lr) * AG_WSTR +
                 ((lane >> 3) & 1) * 16;

    float acc[4][4][4];
#pragma unroll
    for (int mi = 0; mi < 4; mi++)
#pragma unroll
        for (int nq = 0; nq < 4; nq++)
#pragma unroll
            for (int q = 0; q < 4; q++) acc[mi][nq][q] = 0.f;
    float rs[8];
#pragma unroll
    for (int i = 0; i < 8; i++) rs[i] = 0.f;

    for (int s = 0; s < 8; s++) {         // 8 k-chunks (k64 each), 1 N-half
        __syncthreads();
        if (s + 3 < 8) ag_prefetch(Wt, s + 3, (s + 3) & 3, sb);
        else CP_COMMIT();
        CP_WAIT(3);
        __syncthreads();

        uint32_t buf = (uint32_t)(s & 3) * 36864;
#pragma unroll
        for (int k16 = 0; k16 < 4; k16++) {
            uint32_t kxX = s * 128 + k16 * 32;
            uint32_t kxW = k16 * 32;
            uint32_t A[4][4], B[2][4];
#pragma unroll
            for (int mi = 0; mi < 4; mi++) ldsm4(A[mi], aA[mi] + kxX);
#pragma unroll
            for (int nj = 0; nj < 2; nj++) ldsm4(B[nj], bA[nj] + buf + kxW);
#pragma unroll
            for (int mi = 0; mi < 4; mi++)
#pragma unroll
                for (int nj = 0; nj < 2; nj++) {
                    mma_f16(acc[mi][nj * 2],     A[mi], B[nj][0], B[nj][1]);
                    mma_f16(acc[mi][nj * 2 + 1], A[mi], B[nj][2], B[nj][3]);
                }
        }
    }

    // fold the 256-wide N half
    {
        int t2 = (lane & 3) * 2;
#pragma unroll
        for (int mi = 0; mi < 4; mi++)
#pragma unroll
            for (int nq = 0; nq < 4; nq++) {
                int n0 = h * 256 + n_part * 32 + nq * 8 + t2;
                float bb0 = b1s[n0], bb1 = b1s[n0 + 1];
                float ww0 = w2s[n0], ww1 = w2s[n0 + 1];
                float* cc = acc[mi][nq];
                rs[mi * 2 + 0] += fmaxf(cc[0] + bb0, 0.f) * ww0 +
                                  fmaxf(cc[1] + bb1, 0.f) * ww1;
                rs[mi * 2 + 1] += fmaxf(cc[2] + bb0, 0.f) * ww0 +
                                  fmaxf(cc[3] + bb1, 0.f) * ww1;
            }
    }

#pragma unroll
    for (int i = 0; i < 8; i++) {
        rs[i] += __shfl_xor_sync(0xffffffffu, rs[i], 1);
        rs[i] += __shfl_xor_sync(0xffffffffu, rs[i], 2);
    }
    if ((lane & 3) == 0) {
        int g = lane >> 2;
#pragma unroll
        for (int mi = 0; mi < 4; mi++) {
            atomicAdd(&sc[mi * 16 + g],     rs[mi * 2 + 0]);
            atomicAdd(&sc[mi * 16 + 8 + g], rs[mi * 2 + 1]);
        }
    }
    __syncthreads();

    // accumulate partial logits (g_a pre-zeroed by k_zero)
    if (tid < 64)
        atomicAdd(&g_a[rb * 64 + tid], sc[tid] + (h == 0 ? ab2[0] : 0.f));
}

// ---------------- kernel 0: transpose + convert weights ----------------------
__global__ void k_conv(const float* __restrict__ src, __half* __restrict__ dst) {
    __shared__ float tile[64][65];
    int k0 = blockIdx.y * 64, n0 = blockIdx.x * 64;
    for (int i = threadIdx.x; i < 4096; i += 256) {
        int r = i >> 6, cth = i & 63;
        tile[r][cth] = src[(size_t)(k0 + r) * 512 + n0 + cth];
    }
    __syncthreads();
    for (int i = threadIdx.x; i < 4096; i += 256) {
        int r = i >> 6, cth = i & 63;
        dst[(size_t)(n0 + r) * 512 + k0 + cth] = __float2half_rn(tile[cth][r]);
    }
}

// ---------------- kernel 0b: zero g_a (also keeps k_path at ncu slot) ---------
__global__ void k_zero() {
    g_a[blockIdx.x * 64 + threadIdx.x] = 0.f;   // k_agg accumulates into this
}

// ---------------- kernel 3: softmax over 4096 paths ---------------------------
__global__ void k_soft() {
    __shared__ float red[1024];
    int t = threadIdx.x;
    float m = -1e30f;
    for (int i = t; i < NPATHS; i += 1024) m = fmaxf(m, g_a[i]);
    red[t] = m;
    __syncthreads();
    for (int s = 512; s > 0; s >>= 1) {
        if (t < s) red[t] = fmaxf(red[t], red[t + s]);
        __syncthreads();
    }
    float M = red[0];
    __syncthreads();
    float sum = 0.f;
    for (int i = t; i < NPATHS; i += 1024) sum += expf(g_a[i] - M);
    red[t] = sum;
    __syncthreads();
    for (int s = 512; s > 0; s >>= 1) {
        if (t < s) red[t] += red[t + s];
        __syncthreads();
    }
    float S = red[0];
    for (int i = t; i < NPATHS; i += 1024) g_aw[i] = expf(g_a[i] - M) / S;
}

// ---------------- kernel 4: partial weighted sums -----------------------------
__global__ void k_red() {
    int b = blockIdx.x, t = threadIdx.x;
    float a0 = 0.f, a1 = 0.f;
    for (int p = 0; p < 64; p++) {
        int pg = b * 64 + p;
        float w = g_aw[pg];
        const float* row = g_pf + (size_t)pg * 512;
        a0 = fmaf(w, row[t], a0);
        a1 = fmaf(w, row[t + 256], a1);
    }
    g_part[(size_t)b * 512 + t] = a0;
    g_part[(size_t)b * 512 + t + 256] = a1;
}

// ---------------- kernel 5: final reduction -----------------------------------
__global__ void k_fin(float* __restrict__ out) {
    int t = threadIdx.x;
    float s = 0.f;
    for (int b = 0; b < 64; b++) s += g_part[(size_t)b * 512 + t];
    out[t] = s;
}

// ---------------- entry -------------------------------------------------------
extern "C" void kernel_launch(void* const* d_in, const int* in_sizes, int n_in,
                              void* d_out, int out_size) {
    const float* nodes   = (const float*)d_in[0];
    const int*   lengths = (const int*)  d_in[1];
    const float* pW1     = (const float*)d_in[2];
    const float* pb1     = (const float*)d_in[3];
    const float* pw2     = (const float*)d_in[4];
    const float* pb2     = (const float*)d_in[5];
    const float* aW1     = (const float*)d_in[6];
    const float* ab1     = (const float*)d_in[7];
    const float* aw2     = (const float*)d_in[8];
    const float* ab2     = (const float*)d_in[9];
    float* out = (float*)d_out;
    (void)pb2;

    cudaFuncSetAttribute(k_path, cudaFuncAttributeMaxDynamicSharedMemorySize, SMEM_PATH);
    cudaFuncSetAttribute(k_agg,  cudaFuncAttributeMaxDynamicSharedMemorySize, SMEM_AGG);

    __half* w1t;  cudaGetSymbolAddress((void**)&w1t,  g_W1T);
    __half* aw1t; cudaGetSymbolAddress((void**)&aw1t, g_aW1T);

    k_conv<<<dim3(8, 8), 256>>>(pW1, w1t);     // idx 0
    k_conv<<<dim3(8, 8), 256>>>(aW1, aw1t);    // idx 1
    k_zero<<<64, 64>>>();                      // idx 2 (zeroes g_a; ncu slot)
    k_path<<<NPATHS, 128, SMEM_PATH>>>(nodes, lengths, pb1, pw2, pb2);  // idx 3
    k_agg<<<128, 256, SMEM_AGG>>>(ab1, aw2, ab2);                       // idx 4
    k_soft<<<1, 1024>>>();
    k_red<<<64, 256>>>();
    k_fin<<<1, 512>>>(out);
}

// round 15
// speedup vs baseline: 2.3173x; 1.4734x over previous
#include <cuda_runtime.h>
#include <cuda_fp16.h>
#include <cstdint>
#include <cstddef>

// ============================================================================
// AttentionNetwork: P=4096, LMAX=64, D=512, H=512  (fp16 mma.sync path)
// R15 = R12 (best: 518us) + single pair-barrier per macro-iter (CP_WAIT(1)
// before bar.sync subsumes the second barrier), incremental ring-slot
// arithmetic (no %6 in the hot loop), k_red widened to grid 128.
// k_path: M=64/CTA, occ 2, warp tile 32x64, pair-private 6-slot rings.
// ============================================================================

#define NPATHS 4096

// ---------------- device scratch --------------------------------------------
__device__ __half g_W1T[512 * 512];   // pW1^T  [n][k]
__device__ __half g_aW1T[512 * 512];  // aW1^T  [n][k]
__device__ float g_pf[NPATHS * 512];  // paths_fea
__device__ float g_a[NPATHS];         // path logits (accumulated)
__device__ float g_aw[NPATHS];        // path softmax weights
__device__ float g_part[128 * 512];   // reduction partials

// ---------------- k_path SMEM layout (bytes) ----------------------------------
#define OFF_XS   0            // X tile: 64 rows x 1024B, XOR-swizzled
#define OFF_WR   65536        // 4 pairs x 6 slots x 2048B = 49152
#define OFF_SC   65536        // overlays ring after mainloop (64 floats)
#define OFF_WTS  65792        // overlays ring (64 floats)
#define SMEM_PATH 114688      // 112KB -> 2 CTAs/SM

// ---------------- k_agg SMEM layout ------------------------------------------
#define AG_SC    0
#define AG_B1    1024
#define AG_W2    3072
#define AG_XS    5120         // 64 rows x 1040B
#define AG_XSTR  1040
#define AG_WSTR  144
#define OFFWS_AGG 71680
#define SMEM_AGG  (71680 + 4 * 36864)   // 219136

// ---------------- PTX helpers ------------------------------------------------
__device__ __forceinline__ uint32_t smem_u32(const void* p) {
    uint32_t a;
    asm("{ .reg .u64 t; cvta.to.shared.u64 t, %1; cvt.u32.u64 %0, t; }"
        : "=r"(a) : "l"(p));
    return a;
}

__device__ __forceinline__ void ldsm4(uint32_t* r, uint32_t addr) {
    asm volatile("ldmatrix.sync.aligned.m8n8.x4.shared.b16 {%0,%1,%2,%3}, [%4];"
                 : "=r"(r[0]), "=r"(r[1]), "=r"(r[2]), "=r"(r[3]) : "r"(addr));
}

__device__ __forceinline__ void mma_f16(float* c, const uint32_t* a,
                                        uint32_t b0, uint32_t b1) {
    asm volatile(
        "mma.sync.aligned.m16n8k16.row.col.f32.f16.f16.f32 "
        "{%0,%1,%2,%3}, {%4,%5,%6,%7}, {%8,%9}, {%0,%1,%2,%3};"
        : "+f"(c[0]), "+f"(c[1]), "+f"(c[2]), "+f"(c[3])
        : "r"(a[0]), "r"(a[1]), "r"(a[2]), "r"(a[3]), "r"(b0), "r"(b1));
}

#define CP_ASYNC16(dst, src) \
    asm volatile("cp.async.cg.shared.global [%0], [%1], 16;" \
                 :: "r"(dst), "l"(src) : "memory")
#define CP_COMMIT() asm volatile("cp.async.commit_group;" ::: "memory")
#define CP_WAIT(n)  asm volatile("cp.async.wait_group %0;" :: "n"(n) : "memory")
#define BAR_SYNC(id, cnt) \
    asm volatile("bar.sync %0, %1;" :: "r"(id), "r"(cnt) : "memory")

// convert one float4 -> 8B (2x half2) and store to SMEM
__device__ __forceinline__ void sts_f16x4(char* smem, uint32_t off, float4 v) {
    __half2 p0, p1;
    p0.x = __float2half_rn(v.x); p0.y = __float2half_rn(v.y);
    p1.x = __float2half_rn(v.z); p1.y = __float2half_rn(v.w);
    uint2 st;
    st.x = *(uint32_t*)&p0;
    st.y = *(uint32_t*)&p1;
    *(uint2*)(smem + off) = st;
}

// ============================================================================
//                       k_path (R15)
// ============================================================================

// prefetch this warp's halves of W group g (chunks 2g, 2g+1). chunk c:
// rows [nc*256 + pair*64 + half*32, +32), k [kc*16, +16) -> slot c%6.
__device__ __forceinline__ void prefetch_grp(const __half* __restrict__ Wt,
                                             int g, uint32_t pairBase,
                                             int pair, int half, int lane) {
#pragma unroll
    for (int c2 = 0; c2 < 2; c2++) {
        int c = 2 * g + c2;
        int nc = c >> 5, kc = c & 31;
        uint32_t slotbase = pairBase + (uint32_t)(c % 6) * 2048;
        const __half* src =
            Wt + (size_t)(nc * 256 + pair * 64 + half * 32) * 512 + kc * 16;
#pragma unroll
        for (int i = 0; i < 2; i++) {
            int idx = lane + i * 32;      // 0..63
            int nl = half * 32 + (idx >> 1);
            int q  = (idx & 1) << 4;
            uint32_t dst = slotbase + nl * 32 + (q ^ (((nl >> 2) & 1) << 4));
            CP_ASYNC16(dst, src + (size_t)(idx >> 1) * 512 + (q >> 1));
        }
    }
    CP_COMMIT();
}

__global__ void __launch_bounds__(256, 2)
k_path(const float* __restrict__ nodes, const int* __restrict__ lengths,
       const float* __restrict__ pb1, const float* __restrict__ pw2,
       const float* __restrict__ pb2) {
    extern __shared__ char smem[];
    uint32_t sb = smem_u32(smem);
    int tid = threadIdx.x;
    int lane = tid & 31, wid = tid >> 5;
    int m_part = wid & 1;                 // 32-row M slice (also W-half owner)
    int pair   = wid >> 1;                // 0..3 : 64-col slice of 256-N-chunk
    uint32_t pairBase = sb + OFF_WR + pair * (6 * 2048);

    // start this warp's W stream (groups 0,1 = chunks 0..3)
    prefetch_grp(g_W1T, 0, pairBase, pair, m_part, lane);
    prefetch_grp(g_W1T, 1, pairBase, pair, m_part, lane);

    // load X: 64 rows x 512 fp32 -> fp16, XOR-swizzled, stride 1024B
    const float* X = nodes + (size_t)blockIdx.x * 64 * 512;
#pragma unroll 4
    for (int i = 0; i < 32; i++) {
        int idx = tid + i * 256;          // 0..8191 float4 slots
        int m = idx >> 7;                 // 128 float4 per row
        int q = idx & 127;
        float4 v = *(const float4*)(X + (size_t)m * 512 + q * 4);
        uint32_t c = (uint32_t)(q * 8);
        uint32_t off = OFF_XS + m * 1024 + (c ^ (((uint32_t)(m & 7)) << 4));
        sts_f16x4(smem, off, v);
    }
    __syncthreads();                      // publish X

    // per-lane ldmatrix bases
    int lr = lane & 7;
    uint32_t aswz = (uint32_t)lr << 4;                 // X swizzle mask
    uint32_t a16  = (uint32_t)((lane >> 4) & 1) << 4;  // k 16B-half select
    uint32_t aRow[2];
#pragma unroll
    for (int mi = 0; mi < 2; mi++)
        aRow[mi] = sb + OFF_XS +
                   (m_part * 32 + mi * 16 + ((lane >> 3) & 1) * 8 + lr) * 1024;
    uint32_t bB[4];
#pragma unroll
    for (int nj = 0; nj < 4; nj++) {
        int row = nj * 16 + ((lane >> 4) & 1) * 8 + lr;
        uint32_t csel = (uint32_t)((lane >> 3) & 1) << 4;
        uint32_t bswz = (uint32_t)((lr >> 2) & 1) << 4;
        bB[nj] = pairBase + row * 32 + (csel ^ bswz);
    }

    float acc[2][8][4];                   // 64 accumulator regs
#pragma unroll
    for (int mi = 0; mi < 2; mi++)
#pragma unroll
        for (int nq = 0; nq < 8; nq++)
#pragma unroll
            for (int q = 0; q < 4; q++) acc[mi][nq][q] = 0.f;
    float rs[4] = {0.f, 0.f, 0.f, 0.f};

    int barid = 1 + pair;
    int s0 = 0;                           // ring slot of chunk 2i (0,2,4,...)

    // mainloop: 32 macro-iters (k32 each) = 2 N-chunks x 16.
    // ONE pair barrier per iter: CP_WAIT(1) (own group i in) + bar.sync
    // (partner's group i in; both warps done with group i-1, whose slots
    //  the prefetch of group i+2 recycles).
    for (int i = 0; i < 32; i++) {
        CP_WAIT(1);                       // group i landed (i+1 may pend)
        BAR_SYNC(barid, 64);
        if (i + 2 < 32)
            prefetch_grp(g_W1T, i + 2, pairBase, pair, m_part, lane);
        else
            CP_COMMIT();                  // keep group count aligned

        int kc0 = (2 * i) & 31;
        uint32_t slot0 = (uint32_t)s0 * 2048;
#pragma unroll
        for (int step = 0; step < 2; step++) {
            uint32_t kb = (uint32_t)(kc0 + step) * 32;
            uint32_t slotoff = slot0 + (uint32_t)step * 2048;
            uint32_t A[2][4], B[4][4];
#pragma unroll
            for (int mi = 0; mi < 2; mi++)
                ldsm4(A[mi], aRow[mi] + ((kb | a16) ^ aswz));
#pragma unroll
            for (int nj = 0; nj < 4; nj++)
                ldsm4(B[nj], bB[nj] + slotoff);
#pragma unroll
            for (int mi = 0; mi < 2; mi++)
#pragma unroll
                for (int nj = 0; nj < 4; nj++) {
                    mma_f16(acc[mi][nj * 2],     A[mi], B[nj][0], B[nj][1]);
                    mma_f16(acc[mi][nj * 2 + 1], A[mi], B[nj][2], B[nj][3]);
                }
        }

        if ((i & 15) == 15) {
            // fold this 256-wide N chunk into per-row score partials
            int nc = i >> 4;
            int t2 = (lane & 3) * 2;
#pragma unroll
            for (int mi = 0; mi < 2; mi++)
#pragma unroll
                for (int nq = 0; nq < 8; nq++) {
                    int n0 = nc * 256 + pair * 64 + nq * 8 + t2;
                    float2 bb = __ldg((const float2*)(pb1 + n0));
                    float2 ww = __ldg((const float2*)(pw2 + n0));
                    float* cc = acc[mi][nq];
                    rs[mi * 2 + 0] += fmaxf(cc[0] + bb.x, 0.f) * ww.x +
                                      fmaxf(cc[1] + bb.y, 0.f) * ww.y;
                    rs[mi * 2 + 1] += fmaxf(cc[2] + bb.x, 0.f) * ww.x +
                                      fmaxf(cc[3] + bb.y, 0.f) * ww.y;
                    cc[0] = cc[1] = cc[2] = cc[3] = 0.f;
                }
        }

        s0 += 2;
        if (s0 >= 6) s0 -= 6;
    }

    // ring is dead now; overlay sc/wts on it
    __syncthreads();
    float* sc = (float*)(smem + OFF_SC);
    if (tid < 64) sc[tid] = 0.f;
    __syncthreads();

    // reduce the 4 lanes sharing each row, combine the 4 pair warps
#pragma unroll
    for (int i = 0; i < 4; i++) {
        rs[i] += __shfl_xor_sync(0xffffffffu, rs[i], 1);
        rs[i] += __shfl_xor_sync(0xffffffffu, rs[i], 2);
    }
    if ((lane & 3) == 0) {
        int g = lane >> 2;
#pragma unroll
        for (int mi = 0; mi < 2; mi++) {
            atomicAdd(&sc[m_part * 32 + mi * 16 + g],     rs[mi * 2 + 0]);
            atomicAdd(&sc[m_part * 32 + mi * 16 + 8 + g], rs[mi * 2 + 1]);
        }
    }
    __syncthreads();

    // masked softmax over this path's 64 positions
    if (tid < 64) {
        int len = lengths[blockIdx.x];
        float mx = -1e30f;
        for (int j = 0; j < 64; j++) if (j < len) mx = fmaxf(mx, sc[j]);
        float sum = 0.f;
        for (int j = 0; j < 64; j++) if (j < len) sum += expf(sc[j] - mx);
        float w = (tid < len) ? expf(sc[tid] - mx) / sum : 0.f;
        ((float*)(smem + OFF_WTS))[tid] = w;
    }
    __syncthreads();

    // weighted sum of X rows (fp16, swizzled) -> paths_fea
    const float* wts = (const float*)(smem + OFF_WTS);
    {
        int dp = tid;                     // fp16x2 column (0..255)
        float a0 = 0.f, a1 = 0.f;
        uint32_t cbyte = (uint32_t)dp * 4;
#pragma unroll 8
        for (int l = 0; l < 64; l++) {
            uint32_t off = OFF_XS + l * 1024 +
                           (cbyte ^ (((uint32_t)(l & 7)) << 4));
            uint32_t v = *(const uint32_t*)(smem + off);
            __half2 hv = *(__half2*)&v;
            float wl = wts[l];
            a0 = fmaf(wl, __half2float(hv.x), a0);
            a1 = fmaf(wl, __half2float(hv.y), a1);
        }
        float* dst = g_pf + (size_t)blockIdx.x * 512 + dp * 2;
        dst[0] = a0;
        dst[1] = a1;
    }
}

// ============================================================================
//          k_agg (grid 128 = 64 row-blocks x 2 N-halves)
// ============================================================================

__device__ __forceinline__ void ag_prefetch(const __half* __restrict__ Wt,
                                            int s, int buf, uint32_t sb) {
    int tid = threadIdx.x;
    const __half* src = Wt + s * 64;      // chunk s: rows [0,256), k [s*64,+64)
#pragma unroll
    for (int i = 0; i < 8; i++) {
        int idx = tid + i * 256;
        int nl = idx >> 3;
        int q  = idx & 7;
        uint32_t dst = sb + OFFWS_AGG + buf * 36864 + nl * AG_WSTR + q * 16;
        CP_ASYNC16(dst, src + (size_t)nl * 512 + q * 8);
    }
    CP_COMMIT();
}

__global__ void __launch_bounds__(256, 1)
k_agg(const float* __restrict__ ab1, const float* __restrict__ aw2,
      const float* __restrict__ ab2) {
    extern __shared__ char smem[];
    uint32_t sb = smem_u32(smem);
    int tid = threadIdx.x;
    int lane = tid & 31, wid = tid >> 5;
    int n_part = wid;                     // 32-col slice of this 256-N-half
    int rb = blockIdx.x >> 1;             // row block (64 paths)
    int h  = blockIdx.x & 1;              // N half
    const __half* Wt = g_aW1T + (size_t)h * 256 * 512;

    ag_prefetch(Wt, 0, 0, sb);
    ag_prefetch(Wt, 1, 1, sb);
    ag_prefetch(Wt, 2, 2, sb);

    float* b1s = (float*)(smem + AG_B1);
    float* w2s = (float*)(smem + AG_W2);
    float* sc  = (float*)(smem + AG_SC);
    for (int i = tid; i < 512; i += 256) { b1s[i] = ab1[i]; w2s[i] = aw2[i]; }
    if (tid < 64) sc[tid] = 0.f;

    const float* X = g_pf + (size_t)rb * 64 * 512;
#pragma unroll 4
    for (int i = 0; i < 32; i++) {
        int idx = tid + i * 256;
        int m = idx >> 7;
        int q = idx & 127;
        float4 v = *(const float4*)(X + (size_t)m * 512 + q * 4);
        sts_f16x4(smem, AG_XS + m * AG_XSTR + q * 8, v);
    }

    int lr = lane & 7;
    uint32_t aA[4];
#pragma unroll
    for (int mi = 0; mi < 4; mi++)
        aA[mi] = sb + AG_XS +
                 (mi * 16 + ((lane >> 3) & 1) * 8 + lr) * AG_XSTR +
                 (lane >> 4) * 16;
    uint32_t bA[2];
#pragma unroll
    for (int nj = 0; nj < 2; nj++)
        bA[nj] = sb + OFFWS_AGG +
                 (n_part * 32 + nj * 16 + (lane >> 4) * 8 + lr) * AG_WSTR +
                 ((lane >> 3) & 1) * 16;

    float acc[4][4][4];
#pragma unroll
    for (int mi = 0; mi < 4; mi++)
#pragma unroll
        for (int nq = 0; nq < 4; nq++)
#pragma unroll
            for (int q = 0; q < 4; q++) acc[mi][nq][q] = 0.f;
    float rs[8];
#pragma unroll
    for (int i = 0; i < 8; i++) rs[i] = 0.f;

    for (int s = 0; s < 8; s++) {         // 8 k-chunks (k64 each), 1 N-half
        __syncthreads();
        if (s + 3 < 8) ag_prefetch(Wt, s + 3, (s + 3) & 3, sb);
        else CP_COMMIT();
        CP_WAIT(3);
        __syncthreads();

        uint32_t buf = (uint32_t)(s & 3) * 36864;
#pragma unroll
        for (int k16 = 0; k16 < 4; k16++) {
            uint32_t kxX = s * 128 + k16 * 32;
            uint32_t kxW = k16 * 32;
            uint32_t A[4][4], B[2][4];
#pragma unroll
            for (int mi = 0; mi < 4; mi++) ldsm4(A[mi], aA[mi] + kxX);
#pragma unroll
            for (int nj = 0; nj < 2; nj++) ldsm4(B[nj], bA[nj] + buf + kxW);
#pragma unroll
            for (int mi = 0; mi < 4; mi++)
#pragma unroll
                for (int nj = 0; nj < 2; nj++) {
                    mma_f16(acc[mi][nj * 2],     A[mi], B[nj][0], B[nj][1]);
                    mma_f16(acc[mi][nj * 2 + 1], A[mi], B[nj][2], B[nj][3]);
                }
        }
    }

    // fold the 256-wide N half
    {
        int t2 = (lane & 3) * 2;
#pragma unroll
        for (int mi = 0; mi < 4; mi++)
#pragma unroll
            for (int nq = 0; nq < 4; nq++) {
                int n0 = h * 256 + n_part * 32 + nq * 8 + t2;
                float bb0 = b1s[n0], bb1 = b1s[n0 + 1];
                float ww0 = w2s[n0], ww1 = w2s[n0 + 1];
                float* cc = acc[mi][nq];
                rs[mi * 2 + 0] += fmaxf(cc[0] + bb0, 0.f) * ww0 +
                                  fmaxf(cc[1] + bb1, 0.f) * ww1;
                rs[mi * 2 + 1] += fmaxf(cc[2] + bb0, 0.f) * ww0 +
                                  fmaxf(cc[3] + bb1, 0.f) * ww1;
            }
    }

#pragma unroll
    for (int i = 0; i < 8; i++) {
        rs[i] += __shfl_xor_sync(0xffffffffu, rs[i], 1);
        rs[i] += __shfl_xor_sync(0xffffffffu, rs[i], 2);
    }
    if ((lane & 3) == 0) {
        int g = lane >> 2;
#pragma unroll
        for (int mi = 0; mi < 4; mi++) {
            atomicAdd(&sc[mi * 16 + g],     rs[mi * 2 + 0]);
            atomicAdd(&sc[mi * 16 + 8 + g], rs[mi * 2 + 1]);
        }
    }
    __syncthreads();

    // accumulate partial logits (g_a pre-zeroed by k_zero)
    if (tid < 64)
        atomicAdd(&g_a[rb * 64 + tid], sc[tid] + (h == 0 ? ab2[0] : 0.f));
}

// ---------------- kernel 0: transpose + convert weights ----------------------
__global__ void k_conv(const float* __restrict__ src, __half* __restrict__ dst) {
    __shared__ float tile[64][65];
    int k0 = blockIdx.y * 64, n0 = blockIdx.x * 64;
    for (int i = threadIdx.x; i < 4096; i += 256) {
        int r = i >> 6, cth = i & 63;
        tile[r][cth] = src[(size_t)(k0 + r) * 512 + n0 + cth];
    }
    __syncthreads();
    for (int i = threadIdx.x; i < 4096; i += 256) {
        int r = i >> 6, cth = i & 63;
        dst[(size_t)(n0 + r) * 512 + k0 + cth] = __float2half_rn(tile[cth][r]);
    }
}

// ---------------- kernel 0b: zero g_a (also keeps k_path at ncu slot) ---------
__global__ void k_zero() {
    g_a[blockIdx.x * 64 + threadIdx.x] = 0.f;   // k_agg accumulates into this
}

// ---------------- kernel 3: softmax over 4096 paths ---------------------------
__global__ void k_soft() {
    __shared__ float red[1024];
    int t = threadIdx.x;
    float m = -1e30f;
    for (int i = t; i < NPATHS; i += 1024) m = fmaxf(m, g_a[i]);
    red[t] = m;
    __syncthreads();
    for (int s = 512; s > 0; s >>= 1) {
        if (t < s) red[t] = fmaxf(red[t], red[t + s]);
        __syncthreads();
    }
    float M = red[0];
    __syncthreads();
    float sum = 0.f;
    for (int i = t; i < NPATHS; i += 1024) sum += expf(g_a[i] - M);
    red[t] = sum;
    __syncthreads();
    for (int s = 512; s > 0; s >>= 1) {
        if (t < s) red[t] += red[t + s];
        __syncthreads();
    }
    float S = red[0];
    for (int i = t; i < NPATHS; i += 1024) g_aw[i] = expf(g_a[i] - M) / S;
}

// ---------------- kernel 4: partial weighted sums (grid 128) ------------------
__global__ void k_red() {
    int b = blockIdx.x, t = threadIdx.x;
    float a0 = 0.f, a1 = 0.f;
    for (int p = 0; p < 32; p++) {
        int pg = b * 32 + p;
        float w = g_aw[pg];
        const float* row = g_pf + (size_t)pg * 512;
        a0 = fmaf(w, row[t], a0);
        a1 = fmaf(w, row[t + 256], a1);
    }
    g_part[(size_t)b * 512 + t] = a0;
    g_part[(size_t)b * 512 + t + 256] = a1;
}

// ---------------- kernel 5: final reduction -----------------------------------
__global__ void k_fin(float* __restrict__ out) {
    int t = threadIdx.x;
    float s = 0.f;
    for (int b = 0; b < 128; b++) s += g_part[(size_t)b * 512 + t];
    out[t] = s;
}

// ---------------- entry -------------------------------------------------------
extern "C" void kernel_launch(void* const* d_in, const int* in_sizes, int n_in,
                              void* d_out, int out_size) {
    const float* nodes   = (const float*)d_in[0];
    const int*   lengths = (const int*)  d_in[1];
    const float* pW1     = (const float*)d_in[2];
    const float* pb1     = (const float*)d_in[3];
    const float* pw2     = (const float*)d_in[4];
    const float* pb2     = (const float*)d_in[5];
    const float* aW1     = (const float*)d_in[6];
    const float* ab1     = (const float*)d_in[7];
    const float* aw2     = (const float*)d_in[8];
    const float* ab2     = (const float*)d_in[9];
    float* out = (float*)d_out;
    (void)pb2;

    cudaFuncSetAttribute(k_path, cudaFuncAttributeMaxDynamicSharedMemorySize, SMEM_PATH);
    cudaFuncSetAttribute(k_agg,  cudaFuncAttributeMaxDynamicSharedMemorySize, SMEM_AGG);

    __half* w1t;  cudaGetSymbolAddress((void**)&w1t,  g_W1T);
    __half* aw1t; cudaGetSymbolAddress((void**)&aw1t, g_aW1T);

    k_conv<<<dim3(8, 8), 256>>>(pW1, w1t);     // idx 0
    k_conv<<<dim3(8, 8), 256>>>(aW1, aw1t);    // idx 1
    k_zero<<<64, 64>>>();                      // idx 2 (zeroes g_a; ncu slot)
    k_path<<<NPATHS, 256, SMEM_PATH>>>(nodes, lengths, pb1, pw2, pb2);  // idx 3
    k_agg<<<128, 256, SMEM_AGG>>>(ab1, aw2, ab2);                       // idx 4
    k_soft<<<1, 1024>>>();
    k_red<<<128, 256>>>();
    k_fin<<<1, 512>>>(out);
}

// round 16
// speedup vs baseline: 2.3262x; 1.0038x over previous
#include <cuda_runtime.h>
#include <cuda_fp16.h>
#include <cstdint>
#include <cstddef>

// ============================================================================
// AttentionNetwork: P=4096, LMAX=64, D=512, H=512  (fp16 mma.sync path)
// R16 = R15 (best: 493.5us) + batched 12-LDSM per macro-iter (single latency
// exposure before the 32-MMA burst), k_conv collapsed to one launch.
// k_path: M=64/CTA, occ 2, warp tile 32x64, pair-private 6-slot rings,
// one pair-barrier per macro-iter.
// ============================================================================

#define NPATHS 4096

// ---------------- device scratch --------------------------------------------
__device__ __half g_W1T[512 * 512];   // pW1^T  [n][k]
__device__ __half g_aW1T[512 * 512];  // aW1^T  [n][k]
__device__ float g_pf[NPATHS * 512];  // paths_fea
__device__ float g_a[NPATHS];         // path logits (accumulated)
__device__ float g_aw[NPATHS];        // path softmax weights
__device__ float g_part[128 * 512];   // reduction partials

// ---------------- k_path SMEM layout (bytes) ----------------------------------
#define OFF_XS   0            // X tile: 64 rows x 1024B, XOR-swizzled
#define OFF_WR   65536        // 4 pairs x 6 slots x 2048B = 49152
#define OFF_SC   65536        // overlays ring after mainloop (64 floats)
#define OFF_WTS  65792        // overlays ring (64 floats)
#define SMEM_PATH 114688      // 112KB -> 2 CTAs/SM

// ---------------- k_agg SMEM layout ------------------------------------------
#define AG_SC    0
#define AG_B1    1024
#define AG_W2    3072
#define AG_XS    5120         // 64 rows x 1040B
#define AG_XSTR  1040
#define AG_WSTR  144
#define OFFWS_AGG 71680
#define SMEM_AGG  (71680 + 4 * 36864)   // 219136

// ---------------- PTX helpers ------------------------------------------------
__device__ __forceinline__ uint32_t smem_u32(const void* p) {
    uint32_t a;
    asm("{ .reg .u64 t; cvta.to.shared.u64 t, %1; cvt.u32.u64 %0, t; }"
        : "=r"(a) : "l"(p));
    return a;
}

__device__ __forceinline__ void ldsm4(uint32_t* r, uint32_t addr) {
    asm volatile("ldmatrix.sync.aligned.m8n8.x4.shared.b16 {%0,%1,%2,%3}, [%4];"
                 : "=r"(r[0]), "=r"(r[1]), "=r"(r[2]), "=r"(r[3]) : "r"(addr));
}

__device__ __forceinline__ void mma_f16(float* c, const uint32_t* a,
                                        uint32_t b0, uint32_t b1) {
    asm volatile(
        "mma.sync.aligned.m16n8k16.row.col.f32.f16.f16.f32 "
        "{%0,%1,%2,%3}, {%4,%5,%6,%7}, {%8,%9}, {%0,%1,%2,%3};"
        : "+f"(c[0]), "+f"(c[1]), "+f"(c[2]), "+f"(c[3])
        : "r"(a[0]), "r"(a[1]), "r"(a[2]), "r"(a[3]), "r"(b0), "r"(b1));
}

#define CP_ASYNC16(dst, src) \
    asm volatile("cp.async.cg.shared.global [%0], [%1], 16;" \
                 :: "r"(dst), "l"(src) : "memory")
#define CP_COMMIT() asm volatile("cp.async.commit_group;" ::: "memory")
#define CP_WAIT(n)  asm volatile("cp.async.wait_group %0;" :: "n"(n) : "memory")
#define BAR_SYNC(id, cnt) \
    asm volatile("bar.sync %0, %1;" :: "r"(id), "r"(cnt) : "memory")

// convert one float4 -> 8B (2x half2) and store to SMEM
__device__ __forceinline__ void sts_f16x4(char* smem, uint32_t off, float4 v) {
    __half2 p0, p1;
    p0.x = __float2half_rn(v.x); p0.y = __float2half_rn(v.y);
    p1.x = __float2half_rn(v.z); p1.y = __float2half_rn(v.w);
    uint2 st;
    st.x = *(uint32_t*)&p0;
    st.y = *(uint32_t*)&p1;
    *(uint2*)(smem + off) = st;
}

// ============================================================================
//                       k_path (R16)
// ============================================================================

// prefetch this warp's halves of W group g (chunks 2g, 2g+1). chunk c:
// rows [nc*256 + pair*64 + half*32, +32), k [kc*16, +16) -> slot c%6.
__device__ __forceinline__ void prefetch_grp(const __half* __restrict__ Wt,
                                             int g, uint32_t pairBase,
                                             int pair, int half, int lane) {
#pragma unroll
    for (int c2 = 0; c2 < 2; c2++) {
        int c = 2 * g + c2;
        int nc = c >> 5, kc = c & 31;
        uint32_t slotbase = pairBase + (uint32_t)(c % 6) * 2048;
        const __half* src =
            Wt + (size_t)(nc * 256 + pair * 64 + half * 32) * 512 + kc * 16;
#pragma unroll
        for (int i = 0; i < 2; i++) {
            int idx = lane + i * 32;      // 0..63
            int nl = half * 32 + (idx >> 1);
            int q  = (idx & 1) << 4;
            uint32_t dst = slotbase + nl * 32 + (q ^ (((nl >> 2) & 1) << 4));
            CP_ASYNC16(dst, src + (size_t)(idx >> 1) * 512 + (q >> 1));
        }
    }
    CP_COMMIT();
}

__global__ void __launch_bounds__(256, 2)
k_path(const float* __restrict__ nodes, const int* __restrict__ lengths,
       const float* __restrict__ pb1, const float* __restrict__ pw2,
       const float* __restrict__ pb2) {
    extern __shared__ char smem[];
    uint32_t sb = smem_u32(smem);
    int tid = threadIdx.x;
    int lane = tid & 31, wid = tid >> 5;
    int m_part = wid & 1;                 // 32-row M slice (also W-half owner)
    int pair   = wid >> 1;                // 0..3 : 64-col slice of 256-N-chunk
    uint32_t pairBase = sb + OFF_WR + pair * (6 * 2048);

    // start this warp's W stream (groups 0,1 = chunks 0..3)
    prefetch_grp(g_W1T, 0, pairBase, pair, m_part, lane);
    prefetch_grp(g_W1T, 1, pairBase, pair, m_part, lane);

    // load X: 64 rows x 512 fp32 -> fp16, XOR-swizzled, stride 1024B
    const float* X = nodes + (size_t)blockIdx.x * 64 * 512;
#pragma unroll 4
    for (int i = 0; i < 32; i++) {
        int idx = tid + i * 256;          // 0..8191 float4 slots
        int m = idx >> 7;                 // 128 float4 per row
        int q = idx & 127;
        float4 v = *(const float4*)(X + (size_t)m * 512 + q * 4);
        uint32_t c = (uint32_t)(q * 8);
        uint32_t off = OFF_XS + m * 1024 + (c ^ (((uint32_t)(m & 7)) << 4));
        sts_f16x4(smem, off, v);
    }
    __syncthreads();                      // publish X

    // per-lane ldmatrix bases
    int lr = lane & 7;
    uint32_t aswz = (uint32_t)lr << 4;                 // X swizzle mask
    uint32_t a16  = (uint32_t)((lane >> 4) & 1) << 4;  // k 16B-half select
    uint32_t aRow[2];
#pragma unroll
    for (int mi = 0; mi < 2; mi++)
        aRow[mi] = sb + OFF_XS +
                   (m_part * 32 + mi * 16 + ((lane >> 3) & 1) * 8 + lr) * 1024;
    uint32_t bB[4];
#pragma unroll
    for (int nj = 0; nj < 4; nj++) {
        int row = nj * 16 + ((lane >> 4) & 1) * 8 + lr;
        uint32_t csel = (uint32_t)((lane >> 3) & 1) << 4;
        uint32_t bswz = (uint32_t)((lr >> 2) & 1) << 4;
        bB[nj] = pairBase + row * 32 + (csel ^ bswz);
    }

    float acc[2][8][4];                   // 64 accumulator regs
#pragma unroll
    for (int mi = 0; mi < 2; mi++)
#pragma unroll
        for (int nq = 0; nq < 8; nq++)
#pragma unroll
            for (int q = 0; q < 4; q++) acc[mi][nq][q] = 0.f;
    float rs[4] = {0.f, 0.f, 0.f, 0.f};

    int barid = 1 + pair;
    int s0 = 0;                           // ring slot of chunk 2i (0,2,4,...)
    uint32_t kb0 = 0;                     // k-byte offset of chunk 2i (wraps)

    // mainloop: 32 macro-iters (k32 each) = 2 N-chunks x 16.
    // ONE pair barrier per iter; ALL 12 LDSM batched before the 32 MMAs.
    for (int i = 0; i < 32; i++) {
        CP_WAIT(1);                       // group i landed (i+1 may pend)
        BAR_SYNC(barid, 64);
        if (i + 2 < 32)
            prefetch_grp(g_W1T, i + 2, pairBase, pair, m_part, lane);
        else
            CP_COMMIT();                  // keep group count aligned

        uint32_t slot0 = (uint32_t)s0 * 2048;
        uint32_t A[2][2][4], B[2][4][4];  // [step][...]
        // batched fragment loads: 4 A + 8 B, single latency exposure
#pragma unroll
        for (int step = 0; step < 2; step++) {
            uint32_t kx = ((kb0 + (uint32_t)step * 32) | a16) ^ aswz;
#pragma unroll
            for (int mi = 0; mi < 2; mi++)
                ldsm4(A[step][mi], aRow[mi] + kx);
        }
#pragma unroll
        for (int step = 0; step < 2; step++) {
            uint32_t so = slot0 + (uint32_t)step * 2048;
#pragma unroll
            for (int nj = 0; nj < 4; nj++)
                ldsm4(B[step][nj], bB[nj] + so);
        }
        // 32 MMAs
#pragma unroll
        for (int step = 0; step < 2; step++)
#pragma unroll
            for (int mi = 0; mi < 2; mi++)
#pragma unroll
                for (int nj = 0; nj < 4; nj++) {
                    mma_f16(acc[mi][nj * 2],     A[step][mi], B[step][nj][0], B[step][nj][1]);
                    mma_f16(acc[mi][nj * 2 + 1], A[step][mi], B[step][nj][2], B[step][nj][3]);
                }

        if ((i & 15) == 15) {
            // fold this 256-wide N chunk into per-row score partials
            int nc = i >> 4;
            int t2 = (lane & 3) * 2;
#pragma unroll
            for (int mi = 0; mi < 2; mi++)
#pragma unroll
                for (int nq = 0; nq < 8; nq++) {
                    int n0 = nc * 256 + pair * 64 + nq * 8 + t2;
                    float2 bb = __ldg((const float2*)(pb1 + n0));
                    float2 ww = __ldg((const float2*)(pw2 + n0));
                    float* cc = acc[mi][nq];
                    rs[mi * 2 + 0] += fmaxf(cc[0] + bb.x, 0.f) * ww.x +
                                      fmaxf(cc[1] + bb.y, 0.f) * ww.y;
                    rs[mi * 2 + 1] += fmaxf(cc[2] + bb.x, 0.f) * ww.x +
                                      fmaxf(cc[3] + bb.y, 0.f) * ww.y;
                    cc[0] = cc[1] = cc[2] = cc[3] = 0.f;
                }
            kb0 = 0xFFFFFFC0u;            // next iter adds 64 -> wraps to 0
        }

        s0 += 2;
        if (s0 >= 6) s0 -= 6;
        kb0 += 64;
    }

    // ring is dead now; overlay sc/wts on it
    __syncthreads();
    float* sc = (float*)(smem + OFF_SC);
    if (tid < 64) sc[tid] = 0.f;
    __syncthreads();

    // reduce the 4 lanes sharing each row, combine the 4 pair warps
#pragma unroll
    for (int i = 0; i < 4; i++) {
        rs[i] += __shfl_xor_sync(0xffffffffu, rs[i], 1);
        rs[i] += __shfl_xor_sync(0xffffffffu, rs[i], 2);
    }
    if ((lane & 3) == 0) {
        int g = lane >> 2;
#pragma unroll
        for (int mi = 0; mi < 2; mi++) {
            atomicAdd(&sc[m_part * 32 + mi * 16 + g],     rs[mi * 2 + 0]);
            atomicAdd(&sc[m_part * 32 + mi * 16 + 8 + g], rs[mi * 2 + 1]);
        }
    }
    __syncthreads();

    // masked softmax over this path's 64 positions
    if (tid < 64) {
        int len = lengths[blockIdx.x];
        float mx = -1e30f;
        for (int j = 0; j < 64; j++) if (j < len) mx = fmaxf(mx, sc[j]);
        float sum = 0.f;
        for (int j = 0; j < 64; j++) if (j < len) sum += expf(sc[j] - mx);
        float w = (tid < len) ? expf(sc[tid] - mx) / sum : 0.f;
        ((float*)(smem + OFF_WTS))[tid] = w;
    }
    __syncthreads();

    // weighted sum of X rows (fp16, swizzled) -> paths_fea
    const float* wts = (const float*)(smem + OFF_WTS);
    {
        int dp = tid;                     // fp16x2 column (0..255)
        float a0 = 0.f, a1 = 0.f;
        uint32_t cbyte = (uint32_t)dp * 4;
#pragma unroll 8
        for (int l = 0; l < 64; l++) {
            uint32_t off = OFF_XS + l * 1024 +
                           (cbyte ^ (((uint32_t)(l & 7)) << 4));
            uint32_t v = *(const uint32_t*)(smem + off);
            __half2 hv = *(__half2*)&v;
            float wl = wts[l];
            a0 = fmaf(wl, __half2float(hv.x), a0);
            a1 = fmaf(wl, __half2float(hv.y), a1);
        }
        float* dst = g_pf + (size_t)blockIdx.x * 512 + dp * 2;
        dst[0] = a0;
        dst[1] = a1;
    }
}

// ============================================================================
//          k_agg (grid 128 = 64 row-blocks x 2 N-halves)
// ============================================================================

__device__ __forceinline__ void ag_prefetch(const __half* __restrict__ Wt,
                                            int s, int buf, uint32_t sb) {
    int tid = threadIdx.x;
    const __half* src = Wt + s * 64;      // chunk s: rows [0,256), k [s*64,+64)
#pragma unroll
    for (int i = 0; i < 8; i++) {
        int idx = tid + i * 256;
        int nl = idx >> 3;
        int q  = idx & 7;
        uint32_t dst = sb + OFFWS_AGG + buf * 36864 + nl * AG_WSTR + q * 16;
        CP_ASYNC16(dst, src + (size_t)nl * 512 + q * 8);
    }
    CP_COMMIT();
}

__global__ void __launch_bounds__(256, 1)
k_agg(const float* __restrict__ ab1, const float* __restrict__ aw2,
      const float* __restrict__ ab2) {
    extern __shared__ char smem[];
    uint32_t sb = smem_u32(smem);
    int tid = threadIdx.x;
    int lane = tid & 31, wid = tid >> 5;
    int n_part = wid;                     // 32-col slice of this 256-N-half
    int rb = blockIdx.x >> 1;             // row block (64 paths)
    int h  = blockIdx.x & 1;              // N half
    const __half* Wt = g_aW1T + (size_t)h * 256 * 512;

    ag_prefetch(Wt, 0, 0, sb);
    ag_prefetch(Wt, 1, 1, sb);
    ag_prefetch(Wt, 2, 2, sb);

    float* b1s = (float*)(smem + AG_B1);
    float* w2s = (float*)(smem + AG_W2);
    float* sc  = (float*)(smem + AG_SC);
    for (int i = tid; i < 512; i += 256) { b1s[i] = ab1[i]; w2s[i] = aw2[i]; }
    if (tid < 64) sc[tid] = 0.f;

    const float* X = g_pf + (size_t)rb * 64 * 512;
#pragma unroll 4
    for (int i = 0; i < 32; i++) {
        int idx = tid + i * 256;
        int m = idx >> 7;
        int q = idx & 127;
        float4 v = *(const float4*)(X + (size_t)m * 512 + q * 4);
        sts_f16x4(smem, AG_XS + m * AG_XSTR + q * 8, v);
    }

    int lr = lane & 7;
    uint32_t aA[4];
#pragma unroll
    for (int mi = 0; mi < 4; mi++)
        aA[mi] = sb + AG_XS +
                 (mi * 16 + ((lane >> 3) & 1) * 8 + lr) * AG_XSTR +
                 (lane >> 4) * 16;
    uint32_t bA[2];
#pragma unroll
    for (int nj = 0; nj < 2; nj++)
        bA[nj] = sb + OFFWS_AGG +
                 (n_part * 32 + nj * 16 + (lane >> 4) * 8 + lr) * AG_WSTR +
                 ((lane >> 3) & 1) * 16;

    float acc[4][4][4];
#pragma unroll
    for (int mi = 0; mi < 4; mi++)
#pragma unroll
        for (int nq = 0; nq < 4; nq++)
#pragma unroll
            for (int q = 0; q < 4; q++) acc[mi][nq][q] = 0.f;
    float rs[8];
#pragma unroll
    for (int i = 0; i < 8; i++) rs[i] = 0.f;

    for (int s = 0; s < 8; s++) {         // 8 k-chunks (k64 each), 1 N-half
        __syncthreads();
        if (s + 3 < 8) ag_prefetch(Wt, s + 3, (s + 3) & 3, sb);
        else CP_COMMIT();
        CP_WAIT(3);
        __syncthreads();

        uint32_t buf = (uint32_t)(s & 3) * 36864;
#pragma unroll
        for (int k16 = 0; k16 < 4; k16++) {
            uint32_t kxX = s * 128 + k16 * 32;
            uint32_t kxW = k16 * 32;
            uint32_t A[4][4], B[2][4];
#pragma unroll
            for (int mi = 0; mi < 4; mi++) ldsm4(A[mi], aA[mi] + kxX);
#pragma unroll
            for (int nj = 0; nj < 2; nj++) ldsm4(B[nj], bA[nj] + buf + kxW);
#pragma unroll
            for (int mi = 0; mi < 4; mi++)
#pragma unroll
                for (int nj = 0; nj < 2; nj++) {
                    mma_f16(acc[mi][nj * 2],     A[mi], B[nj][0], B[nj][1]);
                    mma_f16(acc[mi][nj * 2 + 1], A[mi], B[nj][2], B[nj][3]);
                }
        }
    }

    // fold the 256-wide N half
    {
        int t2 = (lane & 3) * 2;
#pragma unroll
        for (int mi = 0; mi < 4; mi++)
#pragma unroll
            for (int nq = 0; nq < 4; nq++) {
                int n0 = h * 256 + n_part * 32 + nq * 8 + t2;
                float bb0 = b1s[n0], bb1 = b1s[n0 + 1];
                float ww0 = w2s[n0], ww1 = w2s[n0 + 1];
                float* cc = acc[mi][nq];
                rs[mi * 2 + 0] += fmaxf(cc[0] + bb0, 0.f) * ww0 +
                                  fmaxf(cc[1] + bb1, 0.f) * ww1;
                rs[mi * 2 + 1] += fmaxf(cc[2] + bb0, 0.f) * ww0 +
                                  fmaxf(cc[3] + bb1, 0.f) * ww1;
            }
    }

#pragma unroll
    for (int i = 0; i < 8; i++) {
        rs[i] += __shfl_xor_sync(0xffffffffu, rs[i], 1);
        rs[i] += __shfl_xor_sync(0xffffffffu, rs[i], 2);
    }
    if ((lane & 3) == 0) {
        int g = lane >> 2;
#pragma unroll
        for (int mi = 0; mi < 4; mi++) {
            atomicAdd(&sc[mi * 16 + g],     rs[mi * 2 + 0]);
            atomicAdd(&sc[mi * 16 + 8 + g], rs[mi * 2 + 1]);
        }
    }
    __syncthreads();

    // accumulate partial logits (g_a pre-zeroed by k_zero)
    if (tid < 64)
        atomicAdd(&g_a[rb * 64 + tid], sc[tid] + (h == 0 ? ab2[0] : 0.f));
}

// ---------------- kernel 0: transpose + convert weights (both in one) ---------
__global__ void k_conv(const float* __restrict__ pW1,
                       const float* __restrict__ aW1) {
    __shared__ float tile[64][65];
    const float* src = blockIdx.z ? aW1 : pW1;
    __half* dst = blockIdx.z ? g_aW1T : g_W1T;
    int k0 = blockIdx.y * 64, n0 = blockIdx.x * 64;
    for (int i = threadIdx.x; i < 4096; i += 256) {
        int r = i >> 6, cth = i & 63;
        tile[r][cth] = src[(size_t)(k0 + r) * 512 + n0 + cth];
    }
    __syncthreads();
    for (int i = threadIdx.x; i < 4096; i += 256) {
        int r = i >> 6, cth = i & 63;
        dst[(size_t)(n0 + r) * 512 + k0 + cth] = __float2half_rn(tile[cth][r]);
    }
}

// ---------------- kernel 0b: zero g_a (also keeps k_path at ncu slot) ---------
__global__ void k_zero() {
    g_a[blockIdx.x * 64 + threadIdx.x] = 0.f;   // k_agg accumulates into this
}

// ---------------- kernel 2b: placeholder to keep k_path at ncu capture slot ---
__global__ void k_nop() {}

// ---------------- kernel 3: softmax over 4096 paths ---------------------------
__global__ void k_soft() {
    __shared__ float red[1024];
    int t = threadIdx.x;
    float m = -1e30f;
    for (int i = t; i < NPATHS; i += 1024) m = fmaxf(m, g_a[i]);
    red[t] = m;
    __syncthreads();
    for (int s = 512; s > 0; s >>= 1) {
        if (t < s) red[t] = fmaxf(red[t], red[t + s]);
        __syncthreads();
    }
    float M = red[0];
    __syncthreads();
    float sum = 0.f;
    for (int i = t; i < NPATHS; i += 1024) sum += expf(g_a[i] - M);
    red[t] = sum;
    __syncthreads();
    for (int s = 512; s > 0; s >>= 1) {
        if (t < s) red[t] += red[t + s];
        __syncthreads();
    }
    float S = red[0];
    for (int i = t; i < NPATHS; i += 1024) g_aw[i] = expf(g_a[i] - M) / S;
}

// ---------------- kernel 4: partial weighted sums (grid 128) ------------------
__global__ void k_red() {
    int b = blockIdx.x, t = threadIdx.x;
    float a0 = 0.f, a1 = 0.f;
    for (int p = 0; p < 32; p++) {
        int pg = b * 32 + p;
        float w = g_aw[pg];
        const float* row = g_pf + (size_t)pg * 512;
        a0 = fmaf(w, row[t], a0);
        a1 = fmaf(w, row[t + 256], a1);
    }
    g_part[(size_t)b * 512 + t] = a0;
    g_part[(size_t)b * 512 + t + 256] = a1;
}

// ---------------- kernel 5: final reduction -----------------------------------
__global__ void k_fin(float* __restrict__ out) {
    int t = threadIdx.x;
    float s = 0.f;
    for (int b = 0; b < 128; b++) s += g_part[(size_t)b * 512 + t];
    out[t] = s;
}

// ---------------- entry -------------------------------------------------------
extern "C" void kernel_launch(void* const* d_in, const int* in_sizes, int n_in,
                              void* d_out, int out_size) {
    const float* nodes   = (const float*)d_in[0];
    const int*   lengths = (const int*)  d_in[1];
    const float* pW1     = (const float*)d_in[2];
    const float* pb1     = (const float*)d_in[3];
    const float* pw2     = (const float*)d_in[4];
    const float* pb2     = (const float*)d_in[5];
    const float* aW1     = (const float*)d_in[6];
    const float* ab1     = (const float*)d_in[7];
    const float* aw2     = (const float*)d_in[8];
    const float* ab2     = (const float*)d_in[9];
    float* out = (float*)d_out;
    (void)pb2;

    cudaFuncSetAttribute(k_path, cudaFuncAttributeMaxDynamicSharedMemorySize, SMEM_PATH);
    cudaFuncSetAttribute(k_agg,  cudaFuncAttributeMaxDynamicSharedMemorySize, SMEM_AGG);

    k_conv<<<dim3(8, 8, 2), 256>>>(pW1, aW1);  // idx 0 (both weight matrices)
    k_zero<<<64, 64>>>();                      // idx 1 (zeroes g_a)
    k_nop<<<1, 32>>>();                        // idx 2 (keeps k_path at slot 3)
    k_path<<<NPATHS, 256, SMEM_PATH>>>(nodes, lengths, pb1, pw2, pb2);  // idx 3
    k_agg<<<128, 256, SMEM_AGG>>>(ab1, aw2, ab2);                       // idx 4
    k_soft<<<1, 1024>>>();
    k_red<<<128, 256>>>();
    k_fin<<<1, 512>>>(out);
}

// round 17
// speedup vs baseline: 2.3459x; 1.0085x over previous
#include <cuda_runtime.h>
#include <cuda_fp16.h>
#include <cstdint>
#include <cstddef>

// ============================================================================
// AttentionNetwork: P=4096, LMAX=64, D=512, H=512  (fp16 mma.sync path)
// R17: k_path mainloop reverted to R15 exact form (best measured: 444.7us);
// k_conv stays fused (one launch); k_soft ELIMINATED - each k_red CTA
// recomputes the global softmax stats from g_a (L2-hot) before its partial
// weighted sum. One fewer kernel + ~8us serial softmax removed.
// ============================================================================

#define NPATHS 4096

// ---------------- device scratch --------------------------------------------
__device__ __half g_W1T[512 * 512];   // pW1^T  [n][k]
__device__ __half g_aW1T[512 * 512];  // aW1^T  [n][k]
__device__ float g_pf[NPATHS * 512];  // paths_fea
__device__ float g_a[NPATHS];         // path logits (accumulated)
__device__ float g_part[128 * 512];   // reduction partials

// ---------------- k_path SMEM layout (bytes) ----------------------------------
#define OFF_XS   0            // X tile: 64 rows x 1024B, XOR-swizzled
#define OFF_WR   65536        // 4 pairs x 6 slots x 2048B = 49152
#define OFF_SC   65536        // overlays ring after mainloop (64 floats)
#define OFF_WTS  65792        // overlays ring (64 floats)
#define SMEM_PATH 114688      // 112KB -> 2 CTAs/SM

// ---------------- k_agg SMEM layout ------------------------------------------
#define AG_SC    0
#define AG_B1    1024
#define AG_W2    3072
#define AG_XS    5120         // 64 rows x 1040B
#define AG_XSTR  1040
#define AG_WSTR  144
#define OFFWS_AGG 71680
#define SMEM_AGG  (71680 + 4 * 36864)   // 219136

// ---------------- PTX helpers ------------------------------------------------
__device__ __forceinline__ uint32_t smem_u32(const void* p) {
    uint32_t a;
    asm("{ .reg .u64 t; cvta.to.shared.u64 t, %1; cvt.u32.u64 %0, t; }"
        : "=r"(a) : "l"(p));
    return a;
}

__device__ __forceinline__ void ldsm4(uint32_t* r, uint32_t addr) {
    asm volatile("ldmatrix.sync.aligned.m8n8.x4.shared.b16 {%0,%1,%2,%3}, [%4];"
                 : "=r"(r[0]), "=r"(r[1]), "=r"(r[2]), "=r"(r[3]) : "r"(addr));
}

__device__ __forceinline__ void mma_f16(float* c, const uint32_t* a,
                                        uint32_t b0, uint32_t b1) {
    asm volatile(
        "mma.sync.aligned.m16n8k16.row.col.f32.f16.f16.f32 "
        "{%0,%1,%2,%3}, {%4,%5,%6,%7}, {%8,%9}, {%0,%1,%2,%3};"
        : "+f"(c[0]), "+f"(c[1]), "+f"(c[2]), "+f"(c[3])
        : "r"(a[0]), "r"(a[1]), "r"(a[2]), "r"(a[3]), "r"(b0), "r"(b1));
}

#define CP_ASYNC16(dst, src) \
    asm volatile("cp.async.cg.shared.global [%0], [%1], 16;" \
                 :: "r"(dst), "l"(src) : "memory")
#define CP_COMMIT() asm volatile("cp.async.commit_group;" ::: "memory")
#define CP_WAIT(n)  asm volatile("cp.async.wait_group %0;" :: "n"(n) : "memory")
#define BAR_SYNC(id, cnt) \
    asm volatile("bar.sync %0, %1;" :: "r"(id), "r"(cnt) : "memory")

// convert one float4 -> 8B (2x half2) and store to SMEM
__device__ __forceinline__ void sts_f16x4(char* smem, uint32_t off, float4 v) {
    __half2 p0, p1;
    p0.x = __float2half_rn(v.x); p0.y = __float2half_rn(v.y);
    p1.x = __float2half_rn(v.z); p1.y = __float2half_rn(v.w);
    uint2 st;
    st.x = *(uint32_t*)&p0;
    st.y = *(uint32_t*)&p1;
    *(uint2*)(smem + off) = st;
}

// ============================================================================
//                       k_path (R15 mainloop, exact)
// ============================================================================

// prefetch this warp's halves of W group g (chunks 2g, 2g+1). chunk c:
// rows [nc*256 + pair*64 + half*32, +32), k [kc*16, +16) -> slot c%6.
__device__ __forceinline__ void prefetch_grp(const __half* __restrict__ Wt,
                                             int g, uint32_t pairBase,
                                             int pair, int half, int lane) {
#pragma unroll
    for (int c2 = 0; c2 < 2; c2++) {
        int c = 2 * g + c2;
        int nc = c >> 5, kc = c & 31;
        uint32_t slotbase = pairBase + (uint32_t)(c % 6) * 2048;
        const __half* src =
            Wt + (size_t)(nc * 256 + pair * 64 + half * 32) * 512 + kc * 16;
#pragma unroll
        for (int i = 0; i < 2; i++) {
            int idx = lane + i * 32;      // 0..63
            int nl = half * 32 + (idx >> 1);
            int q  = (idx & 1) << 4;
            uint32_t dst = slotbase + nl * 32 + (q ^ (((nl >> 2) & 1) << 4));
            CP_ASYNC16(dst, src + (size_t)(idx >> 1) * 512 + (q >> 1));
        }
    }
    CP_COMMIT();
}

__global__ void __launch_bounds__(256, 2)
k_path(const float* __restrict__ nodes, const int* __restrict__ lengths,
       const float* __restrict__ pb1, const float* __restrict__ pw2,
       const float* __restrict__ pb2) {
    extern __shared__ char smem[];
    uint32_t sb = smem_u32(smem);
    int tid = threadIdx.x;
    int lane = tid & 31, wid = tid >> 5;
    int m_part = wid & 1;                 // 32-row M slice (also W-half owner)
    int pair   = wid >> 1;                // 0..3 : 64-col slice of 256-N-chunk
    uint32_t pairBase = sb + OFF_WR + pair * (6 * 2048);

    // start this warp's W stream (groups 0,1 = chunks 0..3)
    prefetch_grp(g_W1T, 0, pairBase, pair, m_part, lane);
    prefetch_grp(g_W1T, 1, pairBase, pair, m_part, lane);

    // load X: 64 rows x 512 fp32 -> fp16, XOR-swizzled, stride 1024B
    const float* X = nodes + (size_t)blockIdx.x * 64 * 512;
#pragma unroll 4
    for (int i = 0; i < 32; i++) {
        int idx = tid + i * 256;          // 0..8191 float4 slots
        int m = idx >> 7;                 // 128 float4 per row
        int q = idx & 127;
        float4 v = *(const float4*)(X + (size_t)m * 512 + q * 4);
        uint32_t c = (uint32_t)(q * 8);
        uint32_t off = OFF_XS + m * 1024 + (c ^ (((uint32_t)(m & 7)) << 4));
        sts_f16x4(smem, off, v);
    }
    __syncthreads();                      // publish X

    // per-lane ldmatrix bases
    int lr = lane & 7;
    uint32_t aswz = (uint32_t)lr << 4;                 // X swizzle mask
    uint32_t a16  = (uint32_t)((lane >> 4) & 1) << 4;  // k 16B-half select
    uint32_t aRow[2];
#pragma unroll
    for (int mi = 0; mi < 2; mi++)
        aRow[mi] = sb + OFF_XS +
                   (m_part * 32 + mi * 16 + ((lane >> 3) & 1) * 8 + lr) * 1024;
    uint32_t bB[4];
#pragma unroll
    for (int nj = 0; nj < 4; nj++) {
        int row = nj * 16 + ((lane >> 4) & 1) * 8 + lr;
        uint32_t csel = (uint32_t)((lane >> 3) & 1) << 4;
        uint32_t bswz = (uint32_t)((lr >> 2) & 1) << 4;
        bB[nj] = pairBase + row * 32 + (csel ^ bswz);
    }

    float acc[2][8][4];                   // 64 accumulator regs
#pragma unroll
    for (int mi = 0; mi < 2; mi++)
#pragma unroll
        for (int nq = 0; nq < 8; nq++)
#pragma unroll
            for (int q = 0; q < 4; q++) acc[mi][nq][q] = 0.f;
    float rs[4] = {0.f, 0.f, 0.f, 0.f};

    int barid = 1 + pair;
    int s0 = 0;                           // ring slot of chunk 2i (0,2,4,...)

    // mainloop: 32 macro-iters (k32 each) = 2 N-chunks x 16.
    // ONE pair barrier per iter (R15 form, best measured).
    for (int i = 0; i < 32; i++) {
        CP_WAIT(1);                       // group i landed (i+1 may pend)
        BAR_SYNC(barid, 64);
        if (i + 2 < 32)
            prefetch_grp(g_W1T, i + 2, pairBase, pair, m_part, lane);
        else
            CP_COMMIT();                  // keep group count aligned

        int kc0 = (2 * i) & 31;
        uint32_t slot0 = (uint32_t)s0 * 2048;
#pragma unroll
        for (int step = 0; step < 2; step++) {
            uint32_t kb = (uint32_t)(kc0 + step) * 32;
            uint32_t slotoff = slot0 + (uint32_t)step * 2048;
            uint32_t A[2][4], B[4][4];
#pragma unroll
            for (int mi = 0; mi < 2; mi++)
                ldsm4(A[mi], aRow[mi] + ((kb | a16) ^ aswz));
#pragma unroll
            for (int nj = 0; nj < 4; nj++)
                ldsm4(B[nj], bB[nj] + slotoff);
#pragma unroll
            for (int mi = 0; mi < 2; mi++)
#pragma unroll
                for (int nj = 0; nj < 4; nj++) {
                    mma_f16(acc[mi][nj * 2],     A[mi], B[nj][0], B[nj][1]);
                    mma_f16(acc[mi][nj * 2 + 1], A[mi], B[nj][2], B[nj][3]);
                }
        }

        if ((i & 15) == 15) {
            // fold this 256-wide N chunk into per-row score partials
            int nc = i >> 4;
            int t2 = (lane & 3) * 2;
#pragma unroll
            for (int mi = 0; mi < 2; mi++)
#pragma unroll
                for (int nq = 0; nq < 8; nq++) {
                    int n0 = nc * 256 + pair * 64 + nq * 8 + t2;
                    float2 bb = __ldg((const float2*)(pb1 + n0));
                    float2 ww = __ldg((const float2*)(pw2 + n0));
                    float* cc = acc[mi][nq];
                    rs[mi * 2 + 0] += fmaxf(cc[0] + bb.x, 0.f) * ww.x +
                                      fmaxf(cc[1] + bb.y, 0.f) * ww.y;
                    rs[mi * 2 + 1] += fmaxf(cc[2] + bb.x, 0.f) * ww.x +
                                      fmaxf(cc[3] + bb.y, 0.f) * ww.y;
                    cc[0] = cc[1] = cc[2] = cc[3] = 0.f;
                }
        }

        s0 += 2;
        if (s0 >= 6) s0 -= 6;
    }

    // ring is dead now; overlay sc/wts on it
    __syncthreads();
    float* sc = (float*)(smem + OFF_SC);
    if (tid < 64) sc[tid] = 0.f;
    __syncthreads();

    // reduce the 4 lanes sharing each row, combine the 4 pair warps
#pragma unroll
    for (int i = 0; i < 4; i++) {
        rs[i] += __shfl_xor_sync(0xffffffffu, rs[i], 1);
        rs[i] += __shfl_xor_sync(0xffffffffu, rs[i], 2);
    }
    if ((lane & 3) == 0) {
        int g = lane >> 2;
#pragma unroll
        for (int mi = 0; mi < 2; mi++) {
            atomicAdd(&sc[m_part * 32 + mi * 16 + g],     rs[mi * 2 + 0]);
            atomicAdd(&sc[m_part * 32 + mi * 16 + 8 + g], rs[mi * 2 + 1]);
        }
    }
    __syncthreads();

    // masked softmax over this path's 64 positions
    if (tid < 64) {
        int len = lengths[blockIdx.x];
        float mx = -1e30f;
        for (int j = 0; j < 64; j++) if (j < len) mx = fmaxf(mx, sc[j]);
        float sum = 0.f;
        for (int j = 0; j < 64; j++) if (j < len) sum += expf(sc[j] - mx);
        float w = (tid < len) ? expf(sc[tid] - mx) / sum : 0.f;
        ((float*)(smem + OFF_WTS))[tid] = w;
    }
    __syncthreads();

    // weighted sum of X rows (fp16, swizzled) -> paths_fea
    const float* wts = (const float*)(smem + OFF_WTS);
    {
        int dp = tid;                     // fp16x2 column (0..255)
        float a0 = 0.f, a1 = 0.f;
        uint32_t cbyte = (uint32_t)dp * 4;
#pragma unroll 8
        for (int l = 0; l < 64; l++) {
            uint32_t off = OFF_XS + l * 1024 +
                           (cbyte ^ (((uint32_t)(l & 7)) << 4));
            uint32_t v = *(const uint32_t*)(smem + off);
            __half2 hv = *(__half2*)&v;
            float wl = wts[l];
            a0 = fmaf(wl, __half2float(hv.x), a0);
            a1 = fmaf(wl, __half2float(hv.y), a1);
        }
        float* dst = g_pf + (size_t)blockIdx.x * 512 + dp * 2;
        dst[0] = a0;
        dst[1] = a1;
    }
}

// ============================================================================
//          k_agg (grid 128 = 64 row-blocks x 2 N-halves)
// ============================================================================

__device__ __forceinline__ void ag_prefetch(const __half* __restrict__ Wt,
                                            int s, int buf, uint32_t sb) {
    int tid = threadIdx.x;
    const __half* src = Wt + s * 64;      // chunk s: rows [0,256), k [s*64,+64)
#pragma unroll
    for (int i = 0; i < 8; i++) {
        int idx = tid + i * 256;
        int nl = idx >> 3;
        int q  = idx & 7;
        uint32_t dst = sb + OFFWS_AGG + buf * 36864 + nl * AG_WSTR + q * 16;
        CP_ASYNC16(dst, src + (size_t)nl * 512 + q * 8);
    }
    CP_COMMIT();
}

__global__ void __launch_bounds__(256, 1)
k_agg(const float* __restrict__ ab1, const float* __restrict__ aw2,
      const float* __restrict__ ab2) {
    extern __shared__ char smem[];
    uint32_t sb = smem_u32(smem);
    int tid = threadIdx.x;
    int lane = tid & 31, wid = tid >> 5;
    int n_part = wid;                     // 32-col slice of this 256-N-half
    int rb = blockIdx.x >> 1;             // row block (64 paths)
    int h  = blockIdx.x & 1;              // N half
    const __half* Wt = g_aW1T + (size_t)h * 256 * 512;

    ag_prefetch(Wt, 0, 0, sb);
    ag_prefetch(Wt, 1, 1, sb);
    ag_prefetch(Wt, 2, 2, sb);

    float* b1s = (float*)(smem + AG_B1);
    float* w2s = (float*)(smem + AG_W2);
    float* sc  = (float*)(smem + AG_SC);
    for (int i = tid; i < 512; i += 256) { b1s[i] = ab1[i]; w2s[i] = aw2[i]; }
    if (tid < 64) sc[tid] = 0.f;

    const float* X = g_pf + (size_t)rb * 64 * 512;
#pragma unroll 4
    for (int i = 0; i < 32; i++) {
        int idx = tid + i * 256;
        int m = idx >> 7;
        int q = idx & 127;
        float4 v = *(const float4*)(X + (size_t)m * 512 + q * 4);
        sts_f16x4(smem, AG_XS + m * AG_XSTR + q * 8, v);
    }

    int lr = lane & 7;
    uint32_t aA[4];
#pragma unroll
    for (int mi = 0; mi < 4; mi++)
        aA[mi] = sb + AG_XS +
                 (mi * 16 + ((lane >> 3) & 1) * 8 + lr) * AG_XSTR +
                 (lane >> 4) * 16;
    uint32_t bA[2];
#pragma unroll
    for (int nj = 0; nj < 2; nj++)
        bA[nj] = sb + OFFWS_AGG +
                 (n_part * 32 + nj * 16 + (lane >> 4) * 8 + lr) * AG_WSTR +
                 ((lane >> 3) & 1) * 16;

    float acc[4][4][4];
#pragma unroll
    for (int mi = 0; mi < 4; mi++)
#pragma unroll
        for (int nq = 0; nq < 4; nq++)
#pragma unroll
            for (int q = 0; q < 4; q++) acc[mi][nq][q] = 0.f;
    float rs[8];
#pragma unroll
    for (int i = 0; i < 8; i++) rs[i] = 0.f;

    for (int s = 0; s < 8; s++) {         // 8 k-chunks (k64 each), 1 N-half
        __syncthreads();
        if (s + 3 < 8) ag_prefetch(Wt, s + 3, (s + 3) & 3, sb);
        else CP_COMMIT();
        CP_WAIT(3);
        __syncthreads();

        uint32_t buf = (uint32_t)(s & 3) * 36864;
#pragma unroll
        for (int k16 = 0; k16 < 4; k16++) {
            uint32_t kxX = s * 128 + k16 * 32;
            uint32_t kxW = k16 * 32;
            uint32_t A[4][4], B[2][4];
#pragma unroll
            for (int mi = 0; mi < 4; mi++) ldsm4(A[mi], aA[mi] + kxX);
#pragma unroll
            for (int nj = 0; nj < 2; nj++) ldsm4(B[nj], bA[nj] + buf + kxW);
#pragma unroll
            for (int mi = 0; mi < 4; mi++)
#pragma unroll
                for (int nj = 0; nj < 2; nj++) {
                    mma_f16(acc[mi][nj * 2],     A[mi], B[nj][0], B[nj][1]);
                    mma_f16(acc[mi][nj * 2 + 1], A[mi], B[nj][2], B[nj][3]);
                }
        }
    }

    // fold the 256-wide N half
    {
        int t2 = (lane & 3) * 2;
#pragma unroll
        for (int mi = 0; mi < 4; mi++)
#pragma unroll
            for (int nq = 0; nq < 4; nq++) {
                int n0 = h * 256 + n_part * 32 + nq * 8 + t2;
                float bb0 = b1s[n0], bb1 = b1s[n0 + 1];
                float ww0 = w2s[n0], ww1 = w2s[n0 + 1];
                float* cc = acc[mi][nq];
                rs[mi * 2 + 0] += fmaxf(cc[0] + bb0, 0.f) * ww0 +
                                  fmaxf(cc[1] + bb1, 0.f) * ww1;
                rs[mi * 2 + 1] += fmaxf(cc[2] + bb0, 0.f) * ww0 +
                                  fmaxf(cc[3] + bb1, 0.f) * ww1;
            }
    }

#pragma unroll
    for (int i = 0; i < 8; i++) {
        rs[i] += __shfl_xor_sync(0xffffffffu, rs[i], 1);
        rs[i] += __shfl_xor_sync(0xffffffffu, rs[i], 2);
    }
    if ((lane & 3) == 0) {
        int g = lane >> 2;
#pragma unroll
        for (int mi = 0; mi < 4; mi++) {
            atomicAdd(&sc[mi * 16 + g],     rs[mi * 2 + 0]);
            atomicAdd(&sc[mi * 16 + 8 + g], rs[mi * 2 + 1]);
        }
    }
    __syncthreads();

    // accumulate partial logits (g_a pre-zeroed by k_zero)
    if (tid < 64)
        atomicAdd(&g_a[rb * 64 + tid], sc[tid] + (h == 0 ? ab2[0] : 0.f));
}

// ---------------- kernel 0: transpose + convert weights (both in one) ---------
__global__ void k_conv(const float* __restrict__ pW1,
                       const float* __restrict__ aW1) {
    __shared__ float tile[64][65];
    const float* src = blockIdx.z ? aW1 : pW1;
    __half* dst = blockIdx.z ? g_aW1T : g_W1T;
    int k0 = blockIdx.y * 64, n0 = blockIdx.x * 64;
    for (int i = threadIdx.x; i < 4096; i += 256) {
        int r = i >> 6, cth = i & 63;
        tile[r][cth] = src[(size_t)(k0 + r) * 512 + n0 + cth];
    }
    __syncthreads();
    for (int i = threadIdx.x; i < 4096; i += 256) {
        int r = i >> 6, cth = i & 63;
        dst[(size_t)(n0 + r) * 512 + k0 + cth] = __float2half_rn(tile[cth][r]);
    }
}

// ---------------- kernel 0b: zero g_a -----------------------------------------
__global__ void k_zero() {
    g_a[blockIdx.x * 64 + threadIdx.x] = 0.f;   // k_agg accumulates into this
}

// ---------------- kernel 2b: placeholder to keep k_path at ncu capture slot ---
__global__ void k_nop() {}

// ---------------- kernel 4: softmax stats + partial weighted sums (grid 128) --
__global__ void k_red() {
    __shared__ float red[256];
    int b = blockIdx.x, t = threadIdx.x;

    // global softmax stats over all 4096 logits (g_a is L2-hot, 16KB)
    float m = -1e30f;
    for (int i = t; i < NPATHS; i += 256) m = fmaxf(m, g_a[i]);
    red[t] = m;
    __syncthreads();
    for (int s = 128; s > 0; s >>= 1) {
        if (t < s) red[t] = fmaxf(red[t], red[t + s]);
        __syncthreads();
    }
    float M = red[0];
    __syncthreads();
    float sum = 0.f;
    for (int i = t; i < NPATHS; i += 256) sum += expf(g_a[i] - M);
    red[t] = sum;
    __syncthreads();
    for (int s = 128; s > 0; s >>= 1) {
        if (t < s) red[t] += red[t + s];
        __syncthreads();
    }
    float invS = 1.f / red[0];

    // partial weighted sum over this CTA's 32 paths
    float a0 = 0.f, a1 = 0.f;
    for (int p = 0; p < 32; p++) {
        int pg = b * 32 + p;
        float w = expf(g_a[pg] - M) * invS;
        const float* row = g_pf + (size_t)pg * 512;
        a0 = fmaf(w, row[t], a0);
        a1 = fmaf(w, row[t + 256], a1);
    }
    g_part[(size_t)b * 512 + t] = a0;
    g_part[(size_t)b * 512 + t + 256] = a1;
}

// ---------------- kernel 5: final reduction -----------------------------------
__global__ void k_fin(float* __restrict__ out) {
    int t = threadIdx.x;
    float s = 0.f;
    for (int b = 0; b < 128; b++) s += g_part[(size_t)b * 512 + t];
    out[t] = s;
}

// ---------------- entry -------------------------------------------------------
extern "C" void kernel_launch(void* const* d_in, const int* in_sizes, int n_in,
                              void* d_out, int out_size) {
    const float* nodes   = (const float*)d_in[0];
    const int*   lengths = (const int*)  d_in[1];
    const float* pW1     = (const float*)d_in[2];
    const float* pb1     = (const float*)d_in[3];
    const float* pw2     = (const float*)d_in[4];
    const float* pb2     = (const float*)d_in[5];
    const float* aW1     = (const float*)d_in[6];
    const float* ab1     = (const float*)d_in[7];
    const float* aw2     = (const float*)d_in[8];
    const float* ab2     = (const float*)d_in[9];
    float* out = (float*)d_out;
    (void)pb2;

    cudaFuncSetAttribute(k_path, cudaFuncAttributeMaxDynamicSharedMemorySize, SMEM_PATH);
    cudaFuncSetAttribute(k_agg,  cudaFuncAttributeMaxDynamicSharedMemorySize, SMEM_AGG);

    k_conv<<<dim3(8, 8, 2), 256>>>(pW1, aW1);  // idx 0 (both weight matrices)
    k_zero<<<64, 64>>>();                      // idx 1 (zeroes g_a)
    k_nop<<<1, 32>>>();                        // idx 2 (keeps k_path at slot 3)
    k_path<<<NPATHS, 256, SMEM_PATH>>>(nodes, lengths, pb1, pw2, pb2);  // idx 3
    k_agg<<<128, 256, SMEM_AGG>>>(ab1, aw2, ab2);                       // idx 4
    k_red<<<128, 256>>>();                     // idx 5 (softmax + partials)
    k_fin<<<1, 512>>>(out);                    // idx 6
}